// round 10
// baseline (speedup 1.0000x reference)
#include <cuda_runtime.h>
#include <cuda_bf16.h>
#include <math.h>
#include <stdint.h>

#define BATCH 8
#define SEQ   1024
#define DIM   1024
#define NHEAD 16
#define HDIM  64
#define MTOT  (BATCH*SEQ)           // 8192 tokens
#define SCALE 0.125f                // HD^-0.5
#define CAP   50.0f
#define EPSN  1e-6f
#define NEGINF (-1e30f)

// ---------------- scratch (device globals: no allocation allowed) ----------------
__device__ float g_q[MTOT*DIM];
__device__ float g_k[MTOT*DIM];
__device__ float g_v[MTOT*DIM];
__device__ __nv_bfloat16 g_x_hi[MTOT*DIM];
__device__ __nv_bfloat16 g_x_lo[MTOT*DIM];
__device__ __nv_bfloat16 g_att_hi[MTOT*DIM];
__device__ __nv_bfloat16 g_att_lo[MTOT*DIM];
__device__ __nv_bfloat16 g_w_hi[4][DIM*DIM];   // q,k,v,o
__device__ __nv_bfloat16 g_w_lo[4][DIM*DIM];
// row-major bf16 hi/lo operands for tensor-core attention
__device__ __nv_bfloat16 g_qbh[MTOT*DIM];
__device__ __nv_bfloat16 g_qbl[MTOT*DIM];
__device__ __nv_bfloat16 g_kbh[MTOT*DIM];
__device__ __nv_bfloat16 g_kbl[MTOT*DIM];
__device__ __nv_bfloat16 g_vbh[MTOT*DIM];
__device__ __nv_bfloat16 g_vbl[MTOT*DIM];
__device__ unsigned g_maskbits[SEQ*(SEQ/32)];
__device__ int g_mask_mode;

__device__ __forceinline__ uint32_t smem_u32(const void* p) {
    uint32_t a;
    asm("{ .reg .u64 t; cvta.to.shared.u64 t, %1; cvt.u32.u64 %0, t; }" : "=r"(a) : "l"(p));
    return a;
}
__device__ __forceinline__ unsigned pk2(__nv_bfloat16 a, __nv_bfloat16 b) {
    return (unsigned)__bfloat16_as_ushort(a) | ((unsigned)__bfloat16_as_ushort(b) << 16);
}
__device__ __forceinline__ void pksplit(float x, float y, uint32_t& hi, uint32_t& lo) {
    __nv_bfloat16 hx = __float2bfloat16(x), hy = __float2bfloat16(y);
    hi = pk2(hx, hy);
    lo = pk2(__float2bfloat16(x - __bfloat162float(hx)),
             __float2bfloat16(y - __bfloat162float(hy)));
}
__device__ __forceinline__ void cp16(uint32_t s, const void* g) {
    asm volatile("cp.async.cg.shared.global [%0], [%1], 16;" :: "r"(s), "l"(g));
}
__device__ __forceinline__ void ldm_x4(uint32_t* r, uint32_t a) {
    asm volatile("ldmatrix.sync.aligned.m8n8.x4.shared.b16 {%0,%1,%2,%3}, [%4];"
        : "=r"(r[0]), "=r"(r[1]), "=r"(r[2]), "=r"(r[3]) : "r"(a));
}
__device__ __forceinline__ void ldm_x4_t(uint32_t* r, uint32_t a) {
    asm volatile("ldmatrix.sync.aligned.m8n8.x4.trans.shared.b16 {%0,%1,%2,%3}, [%4];"
        : "=r"(r[0]), "=r"(r[1]), "=r"(r[2]), "=r"(r[3]) : "r"(a));
}
__device__ __forceinline__ void mma16816(float* c, const uint32_t* a, const uint32_t* b) {
    asm volatile("mma.sync.aligned.m16n8k16.row.col.f32.bf16.bf16.f32 "
        "{%0,%1,%2,%3}, {%4,%5,%6,%7}, {%8,%9}, {%0,%1,%2,%3};"
        : "+f"(c[0]), "+f"(c[1]), "+f"(c[2]), "+f"(c[3])
        : "r"(a[0]), "r"(a[1]), "r"(a[2]), "r"(a[3]), "r"(b[0]), "r"(b[1]));
}

// ---------------- mask dtype detection + packing ----------------------------------
__global__ void detect_mask_kernel(const void* m) {
    __shared__ int cu, ci, cf;
    if (threadIdx.x == 0) { cu = 0; ci = 0; cf = 0; }
    __syncthreads();
    const unsigned char* u8 = (const unsigned char*)m;
    const int*   i32 = (const int*)m;
    const float* f32 = (const float*)m;
    int lu = 0;
    for (int i = threadIdx.x; i < SEQ; i += 256)
        if (u8[(size_t)i*(SEQ+1)]) lu++;
    atomicAdd(&cu, lu);
    if (threadIdx.x < 250) {
        if (i32[(size_t)threadIdx.x*(SEQ+1)] != 0)    atomicAdd(&ci, 1);
        if (f32[(size_t)threadIdx.x*(SEQ+1)] == 1.0f) atomicAdd(&cf, 1);
    }
    __syncthreads();
    if (threadIdx.x == 0)
        g_mask_mode = (cu == SEQ) ? 0 : (cf == 250) ? 2 : (ci == 250) ? 1 : 0;
}

__global__ void pack_mask_kernel(const void* m) {
    int w = blockIdx.x * blockDim.x + threadIdx.x;
    if (w >= SEQ*SEQ/32) return;
    int mode = g_mask_mode;
    size_t base = (size_t)w * 32;
    unsigned out = 0;
    if (mode == 0) {
        const unsigned char* p = (const unsigned char*)m;
        #pragma unroll
        for (int j = 0; j < 32; j++) if (p[base+j]) out |= 1u << j;
    } else if (mode == 1) {
        const int* p = (const int*)m;
        #pragma unroll
        for (int j = 0; j < 32; j++) if (p[base+j] != 0) out |= 1u << j;
    } else {
        const float* p = (const float*)m;
        #pragma unroll
        for (int j = 0; j < 32; j++) if (p[base+j] != 0.0f) out |= 1u << j;
    }
    g_maskbits[w] = out;
}

// ---------------- fp32 -> (hi, lo) bf16, row-major --------------------------------
__global__ __launch_bounds__(256) void convert_hilo_kernel(
    const float* __restrict__ src, __nv_bfloat16* __restrict__ hi,
    __nv_bfloat16* __restrict__ lo, int n4)
{
    int t = blockIdx.x * 256 + threadIdx.x;
    if (t >= n4) return;
    float4 v = *(const float4*)(src + (size_t)t * 4);
    float a[4] = {v.x, v.y, v.z, v.w};
    __nv_bfloat16 h[4], l[4];
    #pragma unroll
    for (int j = 0; j < 4; j++) {
        h[j] = __float2bfloat16(a[j]);
        l[j] = __float2bfloat16(a[j] - __bfloat162float(h[j]));
    }
    *(uint2*)(hi + (size_t)t * 4) = make_uint2(pk2(h[0],h[1]), pk2(h[2],h[3]));
    *(uint2*)(lo + (size_t)t * 4) = make_uint2(pk2(l[0],l[1]), pk2(l[2],l[3]));
}

// 4-weight variant: blockIdx.y in {0..3} selects Wq/Wk/Wv/Wo
__global__ __launch_bounds__(256) void convert_w4_kernel(
    const float* w0, const float* w1, const float* w2, const float* w3, int n4)
{
    int t = blockIdx.x * 256 + threadIdx.x;
    if (t >= n4) return;
    int z = blockIdx.y;
    const float* src = (z == 0) ? w0 : (z == 1) ? w1 : (z == 2) ? w2 : w3;
    __nv_bfloat16* hi = g_w_hi[z];
    __nv_bfloat16* lo = g_w_lo[z];
    float4 v = *(const float4*)(src + (size_t)t * 4);
    float a[4] = {v.x, v.y, v.z, v.w};
    __nv_bfloat16 h[4], l[4];
    #pragma unroll
    for (int j = 0; j < 4; j++) {
        h[j] = __float2bfloat16(a[j]);
        l[j] = __float2bfloat16(a[j] - __bfloat162float(h[j]));
    }
    *(uint2*)(hi + (size_t)t * 4) = make_uint2(pk2(h[0],h[1]), pk2(h[2],h[3]));
    *(uint2*)(lo + (size_t)t * 4) = make_uint2(pk2(l[0],l[1]), pk2(l[2],l[3]));
}

// ---------------- split-bf16 HMMA GEMM: C[m][n] = sum_k A[m][k] W[n][k] -----------
// 128x128 CTA tile, 256 threads (8 warps, 4x2), warp tile 32x64.
// K=32 per stage (two k16 slices), 2 stages of 48KB -> ONE barrier pair per 32-K.
// __launch_bounds__(256, 2): regs<=128, 2 CTAs/SM (96KB smem x2 = 192KB <= 228KB).
#define GS_ROW    24
#define GS_ARR    (128*GS_ROW*2)           // 6144 B per array
#define GS_SLICE  (4*GS_ARR)               // 24576 B per k16 slice (Ah,Al,Bh,Bl)
#define GS_STAGE  (2*GS_SLICE)             // 49152 B per K=32 stage
#define GS_TOTAL  (2*GS_STAGE)             // 98304 B

__global__ __launch_bounds__(256, 2) void gemm_hmma_kernel(
    const __nv_bfloat16* __restrict__ ahi, const __nv_bfloat16* __restrict__ alo,
    const __nv_bfloat16* w0h, const __nv_bfloat16* w0l, float* c0,
    const __nv_bfloat16* w1h, const __nv_bfloat16* w1l, float* c1,
    const __nv_bfloat16* w2h, const __nv_bfloat16* w2l, float* c2)
{
    extern __shared__ char sm[];
    uint32_t sb = smem_u32(sm);
    int tid = threadIdx.x, wid = tid >> 5, lane = tid & 31;
    int bn0 = blockIdx.x * 128, bm0 = blockIdx.y * 128, z = blockIdx.z;
    const __nv_bfloat16* wh = (z == 0) ? w0h : (z == 1) ? w1h : w2h;
    const __nv_bfloat16* wl = (z == 0) ? w0l : (z == 1) ? w1l : w2l;
    float* C = (z == 0) ? c0 : (z == 1) ? c1 : c2;

    int wm = wid >> 1, wn = wid & 1;

    int lrow = tid >> 1, lhalf = tid & 1;
    const __nv_bfloat16* gA_hi = ahi + (size_t)(bm0 + lrow) * DIM + lhalf * 8;
    const __nv_bfloat16* gA_lo = alo + (size_t)(bm0 + lrow) * DIM + lhalf * 8;
    const __nv_bfloat16* gB_hi = wh  + (size_t)(bn0 + lrow) * DIM + lhalf * 8;
    const __nv_bfloat16* gB_lo = wl  + (size_t)(bn0 + lrow) * DIM + lhalf * 8;
    uint32_t sOff = (uint32_t)(lrow * GS_ROW + lhalf * 8) * 2;

    float acc[2][8][4];
    #pragma unroll
    for (int i = 0; i < 2; i++)
        #pragma unroll
        for (int j = 0; j < 8; j++)
            #pragma unroll
            for (int r = 0; r < 4; r++) acc[i][j][r] = 0.0f;

    uint32_t aRowByte = (uint32_t)((wm*32 + (lane & 15)) * GS_ROW + (lane >> 4) * 8) * 2;
    uint32_t bRowByte = (uint32_t)((wn*64 + ((lane >> 4) & 1)*8 + (lane & 7)) * GS_ROW
                                   + ((lane >> 3) & 1) * 8) * 2;

    // stage loader: K=32 = two k16 slices; one cp.async group (8 cp16/thread)
    auto load_stage = [&](int st) {
        uint32_t s0 = sb + (uint32_t)(st & 1) * GS_STAGE + sOff;
        #pragma unroll
        for (int sub = 0; sub < 2; sub++) {
            int k0 = st * 32 + sub * 16;
            uint32_t sp = s0 + (uint32_t)sub * GS_SLICE;
            cp16(sp,            gA_hi + k0);
            cp16(sp + GS_ARR,   gA_lo + k0);
            cp16(sp + 2*GS_ARR, gB_hi + k0);
            cp16(sp + 3*GS_ARR, gB_lo + k0);
        }
        asm volatile("cp.async.commit_group;");
    };

    load_stage(0);

    for (int st = 0; st < 32; st++) {
        int cur = st & 1;
        if (st < 31) {
            load_stage(st + 1);
            asm volatile("cp.async.wait_group 1;");
        } else {
            asm volatile("cp.async.wait_group 0;");
        }
        __syncthreads();

        #pragma unroll
        for (int sub = 0; sub < 2; sub++) {
            uint32_t bufb = sb + (uint32_t)cur * GS_STAGE + (uint32_t)sub * GS_SLICE;

            // preload A fragments (hi + lo, both m-frags): 16 regs
            uint32_t ah[2][4], al[2][4];
            #pragma unroll
            for (int mf = 0; mf < 2; mf++) {
                uint32_t addr = bufb + aRowByte + (uint32_t)(mf * 16 * GS_ROW) * 2;
                ldm_x4(ah[mf], addr);
                ldm_x4(al[mf], addr + GS_ARR);
            }
            // stream B per pr (2 n-frags at a time): 8 temp regs
            #pragma unroll
            for (int pr = 0; pr < 4; pr++) {
                uint32_t bhv[4], blv[4];
                uint32_t addr = bufb + 2*GS_ARR + bRowByte + (uint32_t)(pr * 16 * GS_ROW) * 2;
                ldm_x4(bhv, addr);
                ldm_x4(blv, addr + GS_ARR);
                #pragma unroll
                for (int mf = 0; mf < 2; mf++) {
                    mma16816(acc[mf][2*pr],   ah[mf], bhv);
                    mma16816(acc[mf][2*pr+1], ah[mf], bhv+2);
                }
                #pragma unroll
                for (int mf = 0; mf < 2; mf++) {
                    mma16816(acc[mf][2*pr],   ah[mf], blv);
                    mma16816(acc[mf][2*pr+1], ah[mf], blv+2);
                }
                #pragma unroll
                for (int mf = 0; mf < 2; mf++) {
                    mma16816(acc[mf][2*pr],   al[mf], bhv);
                    mma16816(acc[mf][2*pr+1], al[mf], bhv+2);
                }
            }
        }
        __syncthreads();
    }

    int gid4 = lane >> 2, l4 = lane & 3;
    #pragma unroll
    for (int mf = 0; mf < 2; mf++) {
        int row = bm0 + wm*32 + mf*16 + gid4;
        #pragma unroll
        for (int nf = 0; nf < 8; nf++) {
            int col = bn0 + wn*64 + nf*8 + l4*2;
            *(float2*)(C + (size_t)row * DIM + col) =
                make_float2(acc[mf][nf][0], acc[mf][nf][1]);
            *(float2*)(C + (size_t)(row + 8) * DIM + col) =
                make_float2(acc[mf][nf][2], acc[mf][nf][3]);
        }
    }
}

// ---------------- QKNorm + RoPE -> bf16 hi/lo Q,K ---------------------------------
__global__ __launch_bounds__(256) void norm_rope_kernel(
    const float* __restrict__ qg, const float* __restrict__ kg,
    const float* __restrict__ cosb, const float* __restrict__ sinb,
    const int* __restrict__ ridx)
{
    int task = blockIdx.x * 8 + (threadIdx.x >> 5);
    int t = threadIdx.x & 31;
    int which = task >> 17;
    int rem = task & 0x1FFFF;
    int head = rem & (NHEAD - 1);
    int tok  = rem >> 4;
    const float* base = (which ? g_k : g_q) + (size_t)tok * DIM + head * HDIM;
    const float* gamma = which ? kg : qg;
    float x0 = base[t], x1 = base[t + 32];
    float ss = x0*x0 + x1*x1;
    #pragma unroll
    for (int off = 16; off >= 1; off >>= 1)
        ss += __shfl_xor_sync(0xffffffffu, ss, off);
    float r = rsqrtf(ss * (1.0f/64.0f) + EPSN);
    float n0 = x0 * r * gamma[t];
    float n1 = x1 * r * gamma[t + 32];
    int idx = ridx[tok & (SEQ - 1)];
    if (idx >= 0) {
        const float* cp = cosb + (size_t)idx * HDIM;
        const float* sp = sinb + (size_t)idx * HDIM;
        float o0 = n0 * cp[t]      - n1 * sp[t];
        float o1 = n1 * cp[t + 32] + n0 * sp[t + 32];
        n0 = o0; n1 = o1;
    }
    __nv_bfloat16* dh = (which ? g_kbh : g_qbh) + (size_t)tok * DIM + head * HDIM;
    __nv_bfloat16* dl = (which ? g_kbl : g_qbl) + (size_t)tok * DIM + head * HDIM;
    __nv_bfloat16 h0 = __float2bfloat16(n0), h1 = __float2bfloat16(n1);
    dh[t] = h0; dh[t + 32] = h1;
    dl[t]      = __float2bfloat16(n0 - __bfloat162float(h0));
    dl[t + 32] = __float2bfloat16(n1 - __bfloat162float(h1));
}

// ---------------- tensor-core flash attention (R5, passed) ------------------------
#define A_STR   144
#define A_QH    0
#define A_QL    (128*A_STR)
#define A_ST0   (2*128*A_STR)
#define A_KH    0
#define A_KL    18432
#define A_VH    36864
#define A_VL    55296
#define A_STAGE 73728
#define A_SMEM  (A_ST0 + 2*A_STAGE)

__global__ __launch_bounds__(256, 1) void attn_tc_kernel() {
    extern __shared__ char smc[];
    uint32_t sb = smem_u32(smc);
    int tid = threadIdx.x, wid = tid >> 5, lane = tid & 31;
    int qt = blockIdx.x, h = blockIdx.y, b = blockIdx.z;
    int gid4 = lane >> 2, l4 = lane & 3;

    size_t qtok0 = (size_t)(b*SEQ + qt*128);

    #pragma unroll
    for (int i = 0; i < 4; i++) {
        int id = tid + i*256;
        int r = id >> 3, ch = id & 7;
        size_t gq = (qtok0 + r) * DIM + h*HDIM + ch*8;
        cp16(sb + A_QH + r*A_STR + ch*16, g_qbh + gq);
        cp16(sb + A_QL + r*A_STR + ch*16, g_qbl + gq);
        size_t gk = ((size_t)(b*SEQ + r)) * DIM + h*HDIM + ch*8;
        uint32_t st = sb + A_ST0;
        cp16(st + A_KH + r*A_STR + ch*16, g_kbh + gk);
        cp16(st + A_KL + r*A_STR + ch*16, g_kbl + gk);
        cp16(st + A_VH + r*A_STR + ch*16, g_vbh + gk);
        cp16(st + A_VL + r*A_STR + ch*16, g_vbl + gk);
    }
    asm volatile("cp.async.commit_group;");
    asm volatile("cp.async.wait_group 0;");
    __syncthreads();

    uint32_t qfh[4][4], qfl[4][4];
    {
        uint32_t arow = (uint32_t)(wid*16 + (lane & 15));
        uint32_t acol = (uint32_t)((lane >> 4) * 16);
        #pragma unroll
        for (int ks = 0; ks < 4; ks++) {
            ldm_x4(qfh[ks], sb + A_QH + arow*A_STR + ks*32 + acol);
            ldm_x4(qfl[ks], sb + A_QL + arow*A_STR + ks*32 + acol);
        }
    }

    float o[8][4];
    #pragma unroll
    for (int i = 0; i < 8; i++)
        #pragma unroll
        for (int j = 0; j < 4; j++) o[i][j] = 0.0f;
    float m0 = NEGINF, m1 = NEGINF, l0 = 0.0f, l1 = 0.0f;

    int qr0 = qt*128 + wid*16 + gid4;
    uint32_t brow = (uint32_t)(((lane >> 4) & 1)*8 + (lane & 7));
    uint32_t bcol = (uint32_t)(((lane >> 3) & 1) * 16);
    uint32_t vrow = (uint32_t)(((lane >> 3) & 1)*8 + (lane & 7));
    uint32_t vcol = (uint32_t)((lane >> 4) * 16);

    for (int kt = 0; kt < 8; kt++) {
        uint32_t st = sb + A_ST0 + (uint32_t)(kt & 1)*A_STAGE;
        if (kt < 7) {
            uint32_t sn = sb + A_ST0 + (uint32_t)((kt+1) & 1)*A_STAGE;
            #pragma unroll
            for (int i = 0; i < 4; i++) {
                int id = tid + i*256;
                int r = id >> 3, ch = id & 7;
                size_t g = ((size_t)(b*SEQ + (kt+1)*128 + r)) * DIM + h*HDIM + ch*8;
                cp16(sn + A_KH + r*A_STR + ch*16, g_kbh + g);
                cp16(sn + A_KL + r*A_STR + ch*16, g_kbl + g);
                cp16(sn + A_VH + r*A_STR + ch*16, g_vbh + g);
                cp16(sn + A_VL + r*A_STR + ch*16, g_vbl + g);
            }
            asm volatile("cp.async.commit_group;");
            asm volatile("cp.async.wait_group 1;");
        } else {
            asm volatile("cp.async.wait_group 0;");
        }
        __syncthreads();

        float c[16][4];
        #pragma unroll
        for (int i = 0; i < 16; i++)
            #pragma unroll
            for (int j = 0; j < 4; j++) c[i][j] = 0.0f;
        #pragma unroll
        for (int ks = 0; ks < 4; ks++) {
            #pragma unroll
            for (int np = 0; np < 8; np++) {
                uint32_t kb[4], kl[4];
                uint32_t off = (uint32_t)(np*16 + brow)*A_STR + ks*32 + bcol;
                ldm_x4(kb, st + A_KH + off);
                ldm_x4(kl, st + A_KL + off);
                mma16816(c[2*np],   qfh[ks], kb);
                mma16816(c[2*np+1], qfh[ks], kb+2);
                mma16816(c[2*np],   qfh[ks], kl);
                mma16816(c[2*np+1], qfh[ks], kl+2);
                mma16816(c[2*np],   qfl[ks], kb);
                mma16816(c[2*np+1], qfl[ks], kb+2);
            }
        }

        unsigned w0[4], w1[4];
        #pragma unroll
        for (int w = 0; w < 4; w++) {
            w0[w] = g_maskbits[qr0*32 + kt*4 + w];
            w1[w] = g_maskbits[(qr0+8)*32 + kt*4 + w];
        }
        float tm0 = NEGINF, tm1 = NEGINF;
        #pragma unroll
        for (int nf = 0; nf < 16; nf++) {
            int word = nf >> 2;
            int bit = (nf & 3)*8 + l4*2;
            #pragma unroll
            for (int e = 0; e < 4; e++) {
                float y  = c[nf][e] * (SCALE / CAP);
                float y2 = y * y;
                float a  = CAP * (y * (1.0f + y2 * (-0.3333333433f + y2 * 0.1333333403f)));
                unsigned wv = (e < 2) ? w0[word] : w1[word];
                c[nf][e] = ((wv >> (bit + (e & 1))) & 1u) ? a : NEGINF;
            }
            tm0 = fmaxf(tm0, fmaxf(c[nf][0], c[nf][1]));
            tm1 = fmaxf(tm1, fmaxf(c[nf][2], c[nf][3]));
        }
        tm0 = fmaxf(tm0, __shfl_xor_sync(0xffffffffu, tm0, 1));
        tm0 = fmaxf(tm0, __shfl_xor_sync(0xffffffffu, tm0, 2));
        tm1 = fmaxf(tm1, __shfl_xor_sync(0xffffffffu, tm1, 1));
        tm1 = fmaxf(tm1, __shfl_xor_sync(0xffffffffu, tm1, 2));
        float mn0 = fmaxf(m0, tm0), mn1 = fmaxf(m1, tm1);
        float al0 = __expf(m0 - mn0), al1 = __expf(m1 - mn1);
        m0 = mn0; m1 = mn1;
        float rs0 = 0.0f, rs1 = 0.0f;
        #pragma unroll
        for (int nf = 0; nf < 16; nf++) {
            c[nf][0] = __expf(c[nf][0] - mn0);
            c[nf][1] = __expf(c[nf][1] - mn0);
            c[nf][2] = __expf(c[nf][2] - mn1);
            c[nf][3] = __expf(c[nf][3] - mn1);
            rs0 += c[nf][0] + c[nf][1];
            rs1 += c[nf][2] + c[nf][3];
        }
        rs0 += __shfl_xor_sync(0xffffffffu, rs0, 1);
        rs0 += __shfl_xor_sync(0xffffffffu, rs0, 2);
        rs1 += __shfl_xor_sync(0xffffffffu, rs1, 1);
        rs1 += __shfl_xor_sync(0xffffffffu, rs1, 2);
        l0 = l0 * al0 + rs0;
        l1 = l1 * al1 + rs1;
        #pragma unroll
        for (int nf = 0; nf < 8; nf++) {
            o[nf][0] *= al0; o[nf][1] *= al0; o[nf][2] *= al1; o[nf][3] *= al1;
        }

        #pragma unroll
        for (int ks = 0; ks < 8; ks++) {
            uint32_t pah[4], pal[4];
            pksplit(c[2*ks][0],   c[2*ks][1],   pah[0], pal[0]);
            pksplit(c[2*ks][2],   c[2*ks][3],   pah[1], pal[1]);
            pksplit(c[2*ks+1][0], c[2*ks+1][1], pah[2], pal[2]);
            pksplit(c[2*ks+1][2], c[2*ks+1][3], pah[3], pal[3]);
            #pragma unroll
            for (int npv = 0; npv < 4; npv++) {
                uint32_t vb[4], vl[4];
                uint32_t off = (uint32_t)(ks*16 + vrow)*A_STR + npv*32 + vcol;
                ldm_x4_t(vb, st + A_VH + off);
                ldm_x4_t(vl, st + A_VL + off);
                mma16816(o[2*npv],   pah, vb);
                mma16816(o[2*npv+1], pah, vb+2);
                mma16816(o[2*npv],   pah, vl);
                mma16816(o[2*npv+1], pah, vl+2);
                mma16816(o[2*npv],   pal, vb);
                mma16816(o[2*npv+1], pal, vb+2);
            }
        }
        __syncthreads();
    }

    float inv0 = 1.0f / l0, inv1 = 1.0f / l1;
    size_t r0g = (qtok0 + wid*16 + gid4) * DIM + h*HDIM;
    size_t r1g = r0g + (size_t)8 * DIM;
    #pragma unroll
    for (int nf = 0; nf < 8; nf++) {
        int col = nf*8 + l4*2;
        uint32_t hi0, lo0, hi1, lo1;
        pksplit(o[nf][0]*inv0, o[nf][1]*inv0, hi0, lo0);
        pksplit(o[nf][2]*inv1, o[nf][3]*inv1, hi1, lo1);
        *(uint32_t*)(g_att_hi + r0g + col) = hi0;
        *(uint32_t*)(g_att_lo + r0g + col) = lo0;
        *(uint32_t*)(g_att_hi + r1g + col) = hi1;
        *(uint32_t*)(g_att_lo + r1g + col) = lo1;
    }
}

// ---------------- launch ----------------------------------------------------------
extern "C" void kernel_launch(void* const* d_in, const int* in_sizes, int n_in,
                              void* d_out, int out_size)
{
    const float* x    = (const float*)d_in[0];
    const float* Wq   = (const float*)d_in[1];
    const float* Wk   = (const float*)d_in[2];
    const float* Wv   = (const float*)d_in[3];
    const float* Wo   = (const float*)d_in[4];
    const float* qg   = (const float*)d_in[5];
    const float* kg   = (const float*)d_in[6];
    const float* cosb = (const float*)d_in[7];
    const float* sinb = (const float*)d_in[8];
    const int*   ridx = (const int*)d_in[9];
    const void*  mask = d_in[10];
    float* out = (float*)d_out;

    float *gq, *gk, *gv;
    __nv_bfloat16 *xhi, *xlo, *athi, *atlo, *whB, *wlB, *vbh, *vbl;
    cudaGetSymbolAddress((void**)&gq,   g_q);
    cudaGetSymbolAddress((void**)&gk,   g_k);
    cudaGetSymbolAddress((void**)&gv,   g_v);
    cudaGetSymbolAddress((void**)&xhi,  g_x_hi);
    cudaGetSymbolAddress((void**)&xlo,  g_x_lo);
    cudaGetSymbolAddress((void**)&athi, g_att_hi);
    cudaGetSymbolAddress((void**)&atlo, g_att_lo);
    cudaGetSymbolAddress((void**)&whB,  g_w_hi);
    cudaGetSymbolAddress((void**)&wlB,  g_w_lo);
    cudaGetSymbolAddress((void**)&vbh,  g_vbh);
    cudaGetSymbolAddress((void**)&vbl,  g_vbl);
    __nv_bfloat16 *wqh = whB,               *wql = wlB;
    __nv_bfloat16 *wkh = whB + 1*DIM*DIM,   *wkl = wlB + 1*DIM*DIM;
    __nv_bfloat16 *wvh = whB + 2*DIM*DIM,   *wvl = wlB + 2*DIM*DIM;
    __nv_bfloat16 *woh = whB + 3*DIM*DIM,   *wol = wlB + 3*DIM*DIM;

    cudaFuncSetAttribute(gemm_hmma_kernel,
        cudaFuncAttributeMaxDynamicSharedMemorySize, GS_TOTAL);
    cudaFuncSetAttribute(attn_tc_kernel,
        cudaFuncAttributeMaxDynamicSharedMemorySize, A_SMEM);

    // QKV GEMM kept at launch position 4 for ncu capture.
    detect_mask_kernel<<<1, 256>>>(mask);                                          // 1
    convert_hilo_kernel<<<(MTOT*DIM/4 + 255)/256, 256>>>(x, xhi, xlo, MTOT*DIM/4); // 2
    convert_w4_kernel<<<dim3((DIM*DIM/4 + 255)/256, 4), 256>>>(                    // 3
        Wq, Wk, Wv, Wo, DIM*DIM/4);

    gemm_hmma_kernel<<<dim3(8, 64, 3), 256, GS_TOTAL>>>(                           // 4 (QKV)
        xhi, xlo, wqh, wql, gq, wkh, wkl, gk, wvh, wvl, gv);

    pack_mask_kernel<<<(SEQ*SEQ/32 + 255)/256, 256>>>(mask);                       // 5
    norm_rope_kernel<<<(2*MTOT*NHEAD)/8, 256>>>(qg, kg, cosb, sinb, ridx);         // 6
    convert_hilo_kernel<<<(MTOT*DIM/4 + 255)/256, 256>>>(gv, vbh, vbl, MTOT*DIM/4);// 7

    attn_tc_kernel<<<dim3(SEQ/128, NHEAD, BATCH), 256, A_SMEM>>>();                // 8

    gemm_hmma_kernel<<<dim3(8, 64, 1), 256, GS_TOTAL>>>(                           // 9 (O)
        athi, atlo, woh, wol, out, woh, wol, out, woh, wol, out);
}

// round 11
// speedup vs baseline: 1.3196x; 1.3196x over previous
#include <cuda_runtime.h>
#include <cuda_bf16.h>
#include <cuda_fp16.h>
#include <math.h>
#include <stdint.h>

#define BATCH 8
#define SEQ   1024
#define DIM   1024
#define NHEAD 16
#define HDIM  64
#define MTOT  (BATCH*SEQ)           // 8192 tokens
#define SCALE 0.125f                // HD^-0.5
#define CAP   50.0f
#define EPSN  1e-6f
#define NEGINF (-1e30f)

// ---------------- scratch (device globals: no allocation allowed) ----------------
__device__ float g_q[MTOT*DIM];
__device__ float g_k[MTOT*DIM];
__device__ float g_v[MTOT*DIM];
// fp16 hi/lo operands for projection GEMMs (W needs hi only)
__device__ __half g_x_hi[MTOT*DIM];
__device__ __half g_x_lo[MTOT*DIM];
__device__ __half g_att_hi[MTOT*DIM];
__device__ __half g_att_lo[MTOT*DIM];
__device__ __half g_w_hi[4][DIM*DIM];          // q,k,v,o
// row-major bf16 hi/lo operands for tensor-core attention (unchanged)
__device__ __nv_bfloat16 g_qbh[MTOT*DIM];
__device__ __nv_bfloat16 g_qbl[MTOT*DIM];
__device__ __nv_bfloat16 g_kbh[MTOT*DIM];
__device__ __nv_bfloat16 g_kbl[MTOT*DIM];
__device__ __nv_bfloat16 g_vbh[MTOT*DIM];
__device__ __nv_bfloat16 g_vbl[MTOT*DIM];
__device__ unsigned g_maskbits[SEQ*(SEQ/32)];
__device__ int g_mask_mode;

__device__ __forceinline__ uint32_t smem_u32(const void* p) {
    uint32_t a;
    asm("{ .reg .u64 t; cvta.to.shared.u64 t, %1; cvt.u32.u64 %0, t; }" : "=r"(a) : "l"(p));
    return a;
}
__device__ __forceinline__ unsigned pk2(__nv_bfloat16 a, __nv_bfloat16 b) {
    return (unsigned)__bfloat16_as_ushort(a) | ((unsigned)__bfloat16_as_ushort(b) << 16);
}
__device__ __forceinline__ unsigned pk2h(__half a, __half b) {
    return (unsigned)__half_as_ushort(a) | ((unsigned)__half_as_ushort(b) << 16);
}
__device__ __forceinline__ void pksplit(float x, float y, uint32_t& hi, uint32_t& lo) {
    __nv_bfloat16 hx = __float2bfloat16(x), hy = __float2bfloat16(y);
    hi = pk2(hx, hy);
    lo = pk2(__float2bfloat16(x - __bfloat162float(hx)),
             __float2bfloat16(y - __bfloat162float(hy)));
}
__device__ __forceinline__ void pksplit_h(float x, float y, uint32_t& hi, uint32_t& lo) {
    __half hx = __float2half(x), hy = __float2half(y);
    hi = pk2h(hx, hy);
    lo = pk2h(__float2half(x - __half2float(hx)),
              __float2half(y - __half2float(hy)));
}
__device__ __forceinline__ void cp16(uint32_t s, const void* g) {
    asm volatile("cp.async.cg.shared.global [%0], [%1], 16;" :: "r"(s), "l"(g));
}
__device__ __forceinline__ void ldm_x4(uint32_t* r, uint32_t a) {
    asm volatile("ldmatrix.sync.aligned.m8n8.x4.shared.b16 {%0,%1,%2,%3}, [%4];"
        : "=r"(r[0]), "=r"(r[1]), "=r"(r[2]), "=r"(r[3]) : "r"(a));
}
__device__ __forceinline__ void ldm_x4_t(uint32_t* r, uint32_t a) {
    asm volatile("ldmatrix.sync.aligned.m8n8.x4.trans.shared.b16 {%0,%1,%2,%3}, [%4];"
        : "=r"(r[0]), "=r"(r[1]), "=r"(r[2]), "=r"(r[3]) : "r"(a));
}
__device__ __forceinline__ void mma16816(float* c, const uint32_t* a, const uint32_t* b) {
    asm volatile("mma.sync.aligned.m16n8k16.row.col.f32.bf16.bf16.f32 "
        "{%0,%1,%2,%3}, {%4,%5,%6,%7}, {%8,%9}, {%0,%1,%2,%3};"
        : "+f"(c[0]), "+f"(c[1]), "+f"(c[2]), "+f"(c[3])
        : "r"(a[0]), "r"(a[1]), "r"(a[2]), "r"(a[3]), "r"(b[0]), "r"(b[1]));
}
__device__ __forceinline__ void mma16816h(float* c, const uint32_t* a, const uint32_t* b) {
    asm volatile("mma.sync.aligned.m16n8k16.row.col.f32.f16.f16.f32 "
        "{%0,%1,%2,%3}, {%4,%5,%6,%7}, {%8,%9}, {%0,%1,%2,%3};"
        : "+f"(c[0]), "+f"(c[1]), "+f"(c[2]), "+f"(c[3])
        : "r"(a[0]), "r"(a[1]), "r"(a[2]), "r"(a[3]), "r"(b[0]), "r"(b[1]));
}

// ---------------- mask dtype detection + packing ----------------------------------
__global__ void detect_mask_kernel(const void* m) {
    __shared__ int cu, ci, cf;
    if (threadIdx.x == 0) { cu = 0; ci = 0; cf = 0; }
    __syncthreads();
    const unsigned char* u8 = (const unsigned char*)m;
    const int*   i32 = (const int*)m;
    const float* f32 = (const float*)m;
    int lu = 0;
    for (int i = threadIdx.x; i < SEQ; i += 256)
        if (u8[(size_t)i*(SEQ+1)]) lu++;
    atomicAdd(&cu, lu);
    if (threadIdx.x < 250) {
        if (i32[(size_t)threadIdx.x*(SEQ+1)] != 0)    atomicAdd(&ci, 1);
        if (f32[(size_t)threadIdx.x*(SEQ+1)] == 1.0f) atomicAdd(&cf, 1);
    }
    __syncthreads();
    if (threadIdx.x == 0)
        g_mask_mode = (cu == SEQ) ? 0 : (cf == 250) ? 2 : (ci == 250) ? 1 : 0;
}

__global__ void pack_mask_kernel(const void* m) {
    int w = blockIdx.x * blockDim.x + threadIdx.x;
    if (w >= SEQ*SEQ/32) return;
    int mode = g_mask_mode;
    size_t base = (size_t)w * 32;
    unsigned out = 0;
    if (mode == 0) {
        const unsigned char* p = (const unsigned char*)m;
        #pragma unroll
        for (int j = 0; j < 32; j++) if (p[base+j]) out |= 1u << j;
    } else if (mode == 1) {
        const int* p = (const int*)m;
        #pragma unroll
        for (int j = 0; j < 32; j++) if (p[base+j] != 0) out |= 1u << j;
    } else {
        const float* p = (const float*)m;
        #pragma unroll
        for (int j = 0; j < 32; j++) if (p[base+j] != 0.0f) out |= 1u << j;
    }
    g_maskbits[w] = out;
}

// ---------------- fp32 -> (hi, lo) fp16, row-major (GEMM A operands) --------------
__global__ __launch_bounds__(256) void convert_hilo_h_kernel(
    const float* __restrict__ src, __half* __restrict__ hi,
    __half* __restrict__ lo, int n4)
{
    int t = blockIdx.x * 256 + threadIdx.x;
    if (t >= n4) return;
    float4 v = *(const float4*)(src + (size_t)t * 4);
    float a[4] = {v.x, v.y, v.z, v.w};
    __half h[4], l[4];
    #pragma unroll
    for (int j = 0; j < 4; j++) {
        h[j] = __float2half(a[j]);
        l[j] = __float2half(a[j] - __half2float(h[j]));
    }
    *(uint2*)(hi + (size_t)t * 4) = make_uint2(pk2h(h[0],h[1]), pk2h(h[2],h[3]));
    *(uint2*)(lo + (size_t)t * 4) = make_uint2(pk2h(l[0],l[1]), pk2h(l[2],l[3]));
}

// fp32 -> fp16 hi ONLY, 4 weights (blockIdx.y selects)
__global__ __launch_bounds__(256) void convert_w4_kernel(
    const float* w0, const float* w1, const float* w2, const float* w3, int n4)
{
    int t = blockIdx.x * 256 + threadIdx.x;
    if (t >= n4) return;
    int z = blockIdx.y;
    const float* src = (z == 0) ? w0 : (z == 1) ? w1 : (z == 2) ? w2 : w3;
    __half* hi = g_w_hi[z];
    float4 v = *(const float4*)(src + (size_t)t * 4);
    *(uint2*)(hi + (size_t)t * 4) = make_uint2(
        pk2h(__float2half(v.x), __float2half(v.y)),
        pk2h(__float2half(v.z), __float2half(v.w)));
}

// ---------------- fp32 -> (hi, lo) bf16 row-major (attention V) -------------------
__global__ __launch_bounds__(256) void convert_hilo_kernel(
    const float* __restrict__ src, __nv_bfloat16* __restrict__ hi,
    __nv_bfloat16* __restrict__ lo, int n4)
{
    int t = blockIdx.x * 256 + threadIdx.x;
    if (t >= n4) return;
    float4 v = *(const float4*)(src + (size_t)t * 4);
    float a[4] = {v.x, v.y, v.z, v.w};
    __nv_bfloat16 h[4], l[4];
    #pragma unroll
    for (int j = 0; j < 4; j++) {
        h[j] = __float2bfloat16(a[j]);
        l[j] = __float2bfloat16(a[j] - __bfloat162float(h[j]));
    }
    *(uint2*)(hi + (size_t)t * 4) = make_uint2(pk2(h[0],h[1]), pk2(h[2],h[3]));
    *(uint2*)(lo + (size_t)t * 4) = make_uint2(pk2(l[0],l[1]), pk2(l[2],l[3]));
}

// ---------------- split-fp16 HMMA GEMM: C[m][n] = sum_k A[m][k] W[n][k] -----------
// C = Ahi*Whi + Alo*Whi = A*Whi (dropped A*Wlo ~ 2^-12 rel). 2 products -> 2/3 MACs.
// 128x128 CTA tile, 256 threads (8 warps 4x2), k16 steps, 2-stage cp.async.
// Stage arrays: Ahi, Alo, Bhi (18KB/stage). __launch_bounds__(256,2): 2 CTAs/SM.
#define GS_ROW   24
#define GS_ARR   (128*GS_ROW*2)            // 6144 B per array
#define GS_BUF   (3*GS_ARR)                // 18432 B per stage
#define GS_TOTAL (2*GS_BUF)                // 36864 B

__global__ __launch_bounds__(256, 2) void gemm_hmma_kernel(
    const __half* __restrict__ ahi, const __half* __restrict__ alo,
    const __half* w0h, float* c0,
    const __half* w1h, float* c1,
    const __half* w2h, float* c2)
{
    extern __shared__ char sm[];
    uint32_t sb = smem_u32(sm);
    int tid = threadIdx.x, wid = tid >> 5, lane = tid & 31;
    int bn0 = blockIdx.x * 128, bm0 = blockIdx.y * 128, z = blockIdx.z;
    const __half* wh = (z == 0) ? w0h : (z == 1) ? w1h : w2h;
    float* C = (z == 0) ? c0 : (z == 1) ? c1 : c2;

    int wm = wid >> 1, wn = wid & 1;

    int lrow = tid >> 1, lhalf = tid & 1;
    const __half* gA_hi = ahi + (size_t)(bm0 + lrow) * DIM + lhalf * 8;
    const __half* gA_lo = alo + (size_t)(bm0 + lrow) * DIM + lhalf * 8;
    const __half* gB_hi = wh  + (size_t)(bn0 + lrow) * DIM + lhalf * 8;
    uint32_t sOff = (uint32_t)(lrow * GS_ROW + lhalf * 8) * 2;

    float acc[2][8][4];
    #pragma unroll
    for (int i = 0; i < 2; i++)
        #pragma unroll
        for (int j = 0; j < 8; j++)
            #pragma unroll
            for (int r = 0; r < 4; r++) acc[i][j][r] = 0.0f;

    uint32_t aRowByte = (uint32_t)((wm*32 + (lane & 15)) * GS_ROW + (lane >> 4) * 8) * 2;
    uint32_t bRowByte = (uint32_t)((wn*64 + ((lane >> 4) & 1)*8 + (lane & 7)) * GS_ROW
                                   + ((lane >> 3) & 1) * 8) * 2;

    {
        uint32_t s0 = sb + sOff;
        cp16(s0,            gA_hi);
        cp16(s0 + GS_ARR,   gA_lo);
        cp16(s0 + 2*GS_ARR, gB_hi);
        asm volatile("cp.async.commit_group;");
    }

    for (int ks = 0; ks < 64; ks++) {
        int cur = ks & 1;
        if (ks < 63) {
            uint32_t s0 = sb + (cur ^ 1) * GS_BUF + sOff;
            int k0 = (ks + 1) * 16;
            cp16(s0,            gA_hi + k0);
            cp16(s0 + GS_ARR,   gA_lo + k0);
            cp16(s0 + 2*GS_ARR, gB_hi + k0);
            asm volatile("cp.async.commit_group;");
            asm volatile("cp.async.wait_group 1;");
        } else {
            asm volatile("cp.async.wait_group 0;");
        }
        __syncthreads();

        uint32_t bufb = sb + cur * GS_BUF;

        // preload A fragments (hi + lo, both m-frags): 16 regs
        uint32_t ah[2][4], al[2][4];
        #pragma unroll
        for (int mf = 0; mf < 2; mf++) {
            uint32_t addr = bufb + aRowByte + (uint32_t)(mf * 16 * GS_ROW) * 2;
            ldm_x4(ah[mf], addr);
            ldm_x4(al[mf], addr + GS_ARR);
        }
        // stream B hi per pr (2 n-frags at a time): 4 temp regs
        #pragma unroll
        for (int pr = 0; pr < 4; pr++) {
            uint32_t bhv[4];
            uint32_t addr = bufb + 2*GS_ARR + bRowByte + (uint32_t)(pr * 16 * GS_ROW) * 2;
            ldm_x4(bhv, addr);
            #pragma unroll
            for (int mf = 0; mf < 2; mf++) {
                mma16816h(acc[mf][2*pr],   ah[mf], bhv);
                mma16816h(acc[mf][2*pr+1], ah[mf], bhv+2);
            }
            #pragma unroll
            for (int mf = 0; mf < 2; mf++) {
                mma16816h(acc[mf][2*pr],   al[mf], bhv);
                mma16816h(acc[mf][2*pr+1], al[mf], bhv+2);
            }
        }
        __syncthreads();
    }

    int gid4 = lane >> 2, l4 = lane & 3;
    #pragma unroll
    for (int mf = 0; mf < 2; mf++) {
        int row = bm0 + wm*32 + mf*16 + gid4;
        #pragma unroll
        for (int nf = 0; nf < 8; nf++) {
            int col = bn0 + wn*64 + nf*8 + l4*2;
            *(float2*)(C + (size_t)row * DIM + col) =
                make_float2(acc[mf][nf][0], acc[mf][nf][1]);
            *(float2*)(C + (size_t)(row + 8) * DIM + col) =
                make_float2(acc[mf][nf][2], acc[mf][nf][3]);
        }
    }
}

// ---------------- QKNorm + RoPE -> bf16 hi/lo Q,K ---------------------------------
__global__ __launch_bounds__(256) void norm_rope_kernel(
    const float* __restrict__ qg, const float* __restrict__ kg,
    const float* __restrict__ cosb, const float* __restrict__ sinb,
    const int* __restrict__ ridx)
{
    int task = blockIdx.x * 8 + (threadIdx.x >> 5);
    int t = threadIdx.x & 31;
    int which = task >> 17;
    int rem = task & 0x1FFFF;
    int head = rem & (NHEAD - 1);
    int tok  = rem >> 4;
    const float* base = (which ? g_k : g_q) + (size_t)tok * DIM + head * HDIM;
    const float* gamma = which ? kg : qg;
    float x0 = base[t], x1 = base[t + 32];
    float ss = x0*x0 + x1*x1;
    #pragma unroll
    for (int off = 16; off >= 1; off >>= 1)
        ss += __shfl_xor_sync(0xffffffffu, ss, off);
    float r = rsqrtf(ss * (1.0f/64.0f) + EPSN);
    float n0 = x0 * r * gamma[t];
    float n1 = x1 * r * gamma[t + 32];
    int idx = ridx[tok & (SEQ - 1)];
    if (idx >= 0) {
        const float* cp = cosb + (size_t)idx * HDIM;
        const float* sp = sinb + (size_t)idx * HDIM;
        float o0 = n0 * cp[t]      - n1 * sp[t];
        float o1 = n1 * cp[t + 32] + n0 * sp[t + 32];
        n0 = o0; n1 = o1;
    }
    __nv_bfloat16* dh = (which ? g_kbh : g_qbh) + (size_t)tok * DIM + head * HDIM;
    __nv_bfloat16* dl = (which ? g_kbl : g_qbl) + (size_t)tok * DIM + head * HDIM;
    __nv_bfloat16 h0 = __float2bfloat16(n0), h1 = __float2bfloat16(n1);
    dh[t] = h0; dh[t + 32] = h1;
    dl[t]      = __float2bfloat16(n0 - __bfloat162float(h0));
    dl[t + 32] = __float2bfloat16(n1 - __bfloat162float(h1));
}

// ---------------- tensor-core flash attention (bf16 3-product, unchanged math) ----
#define A_STR   144
#define A_QH    0
#define A_QL    (128*A_STR)
#define A_ST0   (2*128*A_STR)
#define A_KH    0
#define A_KL    18432
#define A_VH    36864
#define A_VL    55296
#define A_STAGE 73728
#define A_SMEM  (A_ST0 + 2*A_STAGE)

__global__ __launch_bounds__(256, 1) void attn_tc_kernel() {
    extern __shared__ char smc[];
    uint32_t sb = smem_u32(smc);
    int tid = threadIdx.x, wid = tid >> 5, lane = tid & 31;
    int qt = blockIdx.x, h = blockIdx.y, b = blockIdx.z;
    int gid4 = lane >> 2, l4 = lane & 3;

    size_t qtok0 = (size_t)(b*SEQ + qt*128);

    #pragma unroll
    for (int i = 0; i < 4; i++) {
        int id = tid + i*256;
        int r = id >> 3, ch = id & 7;
        size_t gq = (qtok0 + r) * DIM + h*HDIM + ch*8;
        cp16(sb + A_QH + r*A_STR + ch*16, g_qbh + gq);
        cp16(sb + A_QL + r*A_STR + ch*16, g_qbl + gq);
        size_t gk = ((size_t)(b*SEQ + r)) * DIM + h*HDIM + ch*8;
        uint32_t st = sb + A_ST0;
        cp16(st + A_KH + r*A_STR + ch*16, g_kbh + gk);
        cp16(st + A_KL + r*A_STR + ch*16, g_kbl + gk);
        cp16(st + A_VH + r*A_STR + ch*16, g_vbh + gk);
        cp16(st + A_VL + r*A_STR + ch*16, g_vbl + gk);
    }
    asm volatile("cp.async.commit_group;");
    asm volatile("cp.async.wait_group 0;");
    __syncthreads();

    uint32_t qfh[4][4], qfl[4][4];
    {
        uint32_t arow = (uint32_t)(wid*16 + (lane & 15));
        uint32_t acol = (uint32_t)((lane >> 4) * 16);
        #pragma unroll
        for (int ks = 0; ks < 4; ks++) {
            ldm_x4(qfh[ks], sb + A_QH + arow*A_STR + ks*32 + acol);
            ldm_x4(qfl[ks], sb + A_QL + arow*A_STR + ks*32 + acol);
        }
    }

    float o[8][4];
    #pragma unroll
    for (int i = 0; i < 8; i++)
        #pragma unroll
        for (int j = 0; j < 4; j++) o[i][j] = 0.0f;
    float m0 = NEGINF, m1 = NEGINF, l0 = 0.0f, l1 = 0.0f;

    int qr0 = qt*128 + wid*16 + gid4;
    uint32_t brow = (uint32_t)(((lane >> 4) & 1)*8 + (lane & 7));
    uint32_t bcol = (uint32_t)(((lane >> 3) & 1) * 16);
    uint32_t vrow = (uint32_t)(((lane >> 3) & 1)*8 + (lane & 7));
    uint32_t vcol = (uint32_t)((lane >> 4) * 16);

    for (int kt = 0; kt < 8; kt++) {
        uint32_t st = sb + A_ST0 + (uint32_t)(kt & 1)*A_STAGE;
        if (kt < 7) {
            uint32_t sn = sb + A_ST0 + (uint32_t)((kt+1) & 1)*A_STAGE;
            #pragma unroll
            for (int i = 0; i < 4; i++) {
                int id = tid + i*256;
                int r = id >> 3, ch = id & 7;
                size_t g = ((size_t)(b*SEQ + (kt+1)*128 + r)) * DIM + h*HDIM + ch*8;
                cp16(sn + A_KH + r*A_STR + ch*16, g_kbh + g);
                cp16(sn + A_KL + r*A_STR + ch*16, g_kbl + g);
                cp16(sn + A_VH + r*A_STR + ch*16, g_vbh + g);
                cp16(sn + A_VL + r*A_STR + ch*16, g_vbl + g);
            }
            asm volatile("cp.async.commit_group;");
            asm volatile("cp.async.wait_group 1;");
        } else {
            asm volatile("cp.async.wait_group 0;");
        }
        __syncthreads();

        float c[16][4];
        #pragma unroll
        for (int i = 0; i < 16; i++)
            #pragma unroll
            for (int j = 0; j < 4; j++) c[i][j] = 0.0f;
        #pragma unroll
        for (int ks = 0; ks < 4; ks++) {
            #pragma unroll
            for (int np = 0; np < 8; np++) {
                uint32_t kb[4], kl[4];
                uint32_t off = (uint32_t)(np*16 + brow)*A_STR + ks*32 + bcol;
                ldm_x4(kb, st + A_KH + off);
                ldm_x4(kl, st + A_KL + off);
                mma16816(c[2*np],   qfh[ks], kb);
                mma16816(c[2*np+1], qfh[ks], kb+2);
                mma16816(c[2*np],   qfh[ks], kl);
                mma16816(c[2*np+1], qfh[ks], kl+2);
                mma16816(c[2*np],   qfl[ks], kb);
                mma16816(c[2*np+1], qfl[ks], kb+2);
            }
        }

        unsigned w0[4], w1[4];
        #pragma unroll
        for (int w = 0; w < 4; w++) {
            w0[w] = g_maskbits[qr0*32 + kt*4 + w];
            w1[w] = g_maskbits[(qr0+8)*32 + kt*4 + w];
        }
        float tm0 = NEGINF, tm1 = NEGINF;
        #pragma unroll
        for (int nf = 0; nf < 16; nf++) {
            int word = nf >> 2;
            int bit = (nf & 3)*8 + l4*2;
            #pragma unroll
            for (int e = 0; e < 4; e++) {
                float y  = c[nf][e] * (SCALE / CAP);
                float y2 = y * y;
                float a  = CAP * (y * (1.0f + y2 * (-0.3333333433f + y2 * 0.1333333403f)));
                unsigned wv = (e < 2) ? w0[word] : w1[word];
                c[nf][e] = ((wv >> (bit + (e & 1))) & 1u) ? a : NEGINF;
            }
            tm0 = fmaxf(tm0, fmaxf(c[nf][0], c[nf][1]));
            tm1 = fmaxf(tm1, fmaxf(c[nf][2], c[nf][3]));
        }
        tm0 = fmaxf(tm0, __shfl_xor_sync(0xffffffffu, tm0, 1));
        tm0 = fmaxf(tm0, __shfl_xor_sync(0xffffffffu, tm0, 2));
        tm1 = fmaxf(tm1, __shfl_xor_sync(0xffffffffu, tm1, 1));
        tm1 = fmaxf(tm1, __shfl_xor_sync(0xffffffffu, tm1, 2));
        float mn0 = fmaxf(m0, tm0), mn1 = fmaxf(m1, tm1);
        float al0 = __expf(m0 - mn0), al1 = __expf(m1 - mn1);
        m0 = mn0; m1 = mn1;
        float rs0 = 0.0f, rs1 = 0.0f;
        #pragma unroll
        for (int nf = 0; nf < 16; nf++) {
            c[nf][0] = __expf(c[nf][0] - mn0);
            c[nf][1] = __expf(c[nf][1] - mn0);
            c[nf][2] = __expf(c[nf][2] - mn1);
            c[nf][3] = __expf(c[nf][3] - mn1);
            rs0 += c[nf][0] + c[nf][1];
            rs1 += c[nf][2] + c[nf][3];
        }
        rs0 += __shfl_xor_sync(0xffffffffu, rs0, 1);
        rs0 += __shfl_xor_sync(0xffffffffu, rs0, 2);
        rs1 += __shfl_xor_sync(0xffffffffu, rs1, 1);
        rs1 += __shfl_xor_sync(0xffffffffu, rs1, 2);
        l0 = l0 * al0 + rs0;
        l1 = l1 * al1 + rs1;
        #pragma unroll
        for (int nf = 0; nf < 8; nf++) {
            o[nf][0] *= al0; o[nf][1] *= al0; o[nf][2] *= al1; o[nf][3] *= al1;
        }

        #pragma unroll
        for (int ks = 0; ks < 8; ks++) {
            uint32_t pah[4], pal[4];
            pksplit(c[2*ks][0],   c[2*ks][1],   pah[0], pal[0]);
            pksplit(c[2*ks][2],   c[2*ks][3],   pah[1], pal[1]);
            pksplit(c[2*ks+1][0], c[2*ks+1][1], pah[2], pal[2]);
            pksplit(c[2*ks+1][2], c[2*ks+1][3], pah[3], pal[3]);
            #pragma unroll
            for (int npv = 0; npv < 4; npv++) {
                uint32_t vb[4], vl[4];
                uint32_t off = (uint32_t)(ks*16 + vrow)*A_STR + npv*32 + vcol;
                ldm_x4_t(vb, st + A_VH + off);
                ldm_x4_t(vl, st + A_VL + off);
                mma16816(o[2*npv],   pah, vb);
                mma16816(o[2*npv+1], pah, vb+2);
                mma16816(o[2*npv],   pah, vl);
                mma16816(o[2*npv+1], pah, vl+2);
                mma16816(o[2*npv],   pal, vb);
                mma16816(o[2*npv+1], pal, vb+2);
            }
        }
        __syncthreads();
    }

    // epilogue: normalize, write (hi, lo) fp16 for the O projection
    float inv0 = 1.0f / l0, inv1 = 1.0f / l1;
    size_t r0g = (qtok0 + wid*16 + gid4) * DIM + h*HDIM;
    size_t r1g = r0g + (size_t)8 * DIM;
    #pragma unroll
    for (int nf = 0; nf < 8; nf++) {
        int col = nf*8 + l4*2;
        uint32_t hi0, lo0, hi1, lo1;
        pksplit_h(o[nf][0]*inv0, o[nf][1]*inv0, hi0, lo0);
        pksplit_h(o[nf][2]*inv1, o[nf][3]*inv1, hi1, lo1);
        *(uint32_t*)(g_att_hi + r0g + col) = hi0;
        *(uint32_t*)(g_att_lo + r0g + col) = lo0;
        *(uint32_t*)(g_att_hi + r1g + col) = hi1;
        *(uint32_t*)(g_att_lo + r1g + col) = lo1;
    }
}

// ---------------- launch ----------------------------------------------------------
extern "C" void kernel_launch(void* const* d_in, const int* in_sizes, int n_in,
                              void* d_out, int out_size)
{
    const float* x    = (const float*)d_in[0];
    const float* Wq   = (const float*)d_in[1];
    const float* Wk   = (const float*)d_in[2];
    const float* Wv   = (const float*)d_in[3];
    const float* Wo   = (const float*)d_in[4];
    const float* qg   = (const float*)d_in[5];
    const float* kg   = (const float*)d_in[6];
    const float* cosb = (const float*)d_in[7];
    const float* sinb = (const float*)d_in[8];
    const int*   ridx = (const int*)d_in[9];
    const void*  mask = d_in[10];
    float* out = (float*)d_out;

    float *gq, *gk, *gv;
    __half *xhi, *xlo, *athi, *atlo, *whB;
    __nv_bfloat16 *vbh, *vbl;
    cudaGetSymbolAddress((void**)&gq,   g_q);
    cudaGetSymbolAddress((void**)&gk,   g_k);
    cudaGetSymbolAddress((void**)&gv,   g_v);
    cudaGetSymbolAddress((void**)&xhi,  g_x_hi);
    cudaGetSymbolAddress((void**)&xlo,  g_x_lo);
    cudaGetSymbolAddress((void**)&athi, g_att_hi);
    cudaGetSymbolAddress((void**)&atlo, g_att_lo);
    cudaGetSymbolAddress((void**)&whB,  g_w_hi);
    cudaGetSymbolAddress((void**)&vbh,  g_vbh);
    cudaGetSymbolAddress((void**)&vbl,  g_vbl);
    __half *wqh = whB;
    __half *wkh = whB + 1*DIM*DIM;
    __half *wvh = whB + 2*DIM*DIM;
    __half *woh = whB + 3*DIM*DIM;

    cudaFuncSetAttribute(gemm_hmma_kernel,
        cudaFuncAttributeMaxDynamicSharedMemorySize, GS_TOTAL);
    cudaFuncSetAttribute(attn_tc_kernel,
        cudaFuncAttributeMaxDynamicSharedMemorySize, A_SMEM);

    // QKV GEMM kept at launch position 4 for ncu capture.
    detect_mask_kernel<<<1, 256>>>(mask);                                            // 1
    convert_hilo_h_kernel<<<(MTOT*DIM/4 + 255)/256, 256>>>(x, xhi, xlo, MTOT*DIM/4); // 2
    convert_w4_kernel<<<dim3((DIM*DIM/4 + 255)/256, 4), 256>>>(                      // 3
        Wq, Wk, Wv, Wo, DIM*DIM/4);

    gemm_hmma_kernel<<<dim3(8, 64, 3), 256, GS_TOTAL>>>(                             // 4 (QKV)
        xhi, xlo, wqh, gq, wkh, gk, wvh, gv);

    pack_mask_kernel<<<(SEQ*SEQ/32 + 255)/256, 256>>>(mask);                         // 5
    norm_rope_kernel<<<(2*MTOT*NHEAD)/8, 256>>>(qg, kg, cosb, sinb, ridx);           // 6
    convert_hilo_kernel<<<(MTOT*DIM/4 + 255)/256, 256>>>(gv, vbh, vbl, MTOT*DIM/4);  // 7

    attn_tc_kernel<<<dim3(SEQ/128, NHEAD, BATCH), 256, A_SMEM>>>();                  // 8

    gemm_hmma_kernel<<<dim3(8, 64, 1), 256, GS_TOTAL>>>(                             // 9 (O)
        athi, atlo, woh, out, woh, out, woh, out);
}

// round 12
// speedup vs baseline: 1.4511x; 1.0997x over previous
#include <cuda_runtime.h>
#include <cuda_bf16.h>
#include <cuda_fp16.h>
#include <math.h>
#include <stdint.h>

#define BATCH 8
#define SEQ   1024
#define DIM   1024
#define NHEAD 16
#define HDIM  64
#define MTOT  (BATCH*SEQ)           // 8192 tokens
#define SCALE 0.125f                // HD^-0.5
#define CAP   50.0f
#define EPSN  1e-6f
#define NEGINF (-1e30f)

// ---------------- scratch (device globals: no allocation allowed) ----------------
__device__ float g_q[MTOT*DIM];
__device__ float g_k[MTOT*DIM];
__device__ float g_v[MTOT*DIM];
// fp16 hi/lo operands for projection GEMMs (W needs hi only)
__device__ __half g_x_hi[MTOT*DIM];
__device__ __half g_x_lo[MTOT*DIM];
__device__ __half g_att_hi[MTOT*DIM];
__device__ __half g_att_lo[MTOT*DIM];
__device__ __half g_w_hi[4][DIM*DIM];          // q,k,v,o
// fp16 operands for tensor-core attention: Q hi/lo, K hi, V hi
__device__ __half g_qbh[MTOT*DIM];
__device__ __half g_qbl[MTOT*DIM];
__device__ __half g_kbh[MTOT*DIM];
__device__ __half g_vbh[MTOT*DIM];
__device__ unsigned g_maskbits[SEQ*(SEQ/32)];
__device__ int g_mask_mode;

__device__ __forceinline__ uint32_t smem_u32(const void* p) {
    uint32_t a;
    asm("{ .reg .u64 t; cvta.to.shared.u64 t, %1; cvt.u32.u64 %0, t; }" : "=r"(a) : "l"(p));
    return a;
}
__device__ __forceinline__ unsigned pk2h(__half a, __half b) {
    return (unsigned)__half_as_ushort(a) | ((unsigned)__half_as_ushort(b) << 16);
}
__device__ __forceinline__ void pksplit_h(float x, float y, uint32_t& hi, uint32_t& lo) {
    __half hx = __float2half(x), hy = __float2half(y);
    hi = pk2h(hx, hy);
    lo = pk2h(__float2half(x - __half2float(hx)),
              __float2half(y - __half2float(hy)));
}
__device__ __forceinline__ void cp16(uint32_t s, const void* g) {
    asm volatile("cp.async.cg.shared.global [%0], [%1], 16;" :: "r"(s), "l"(g));
}
__device__ __forceinline__ void ldm_x4(uint32_t* r, uint32_t a) {
    asm volatile("ldmatrix.sync.aligned.m8n8.x4.shared.b16 {%0,%1,%2,%3}, [%4];"
        : "=r"(r[0]), "=r"(r[1]), "=r"(r[2]), "=r"(r[3]) : "r"(a));
}
__device__ __forceinline__ void ldm_x4_t(uint32_t* r, uint32_t a) {
    asm volatile("ldmatrix.sync.aligned.m8n8.x4.trans.shared.b16 {%0,%1,%2,%3}, [%4];"
        : "=r"(r[0]), "=r"(r[1]), "=r"(r[2]), "=r"(r[3]) : "r"(a));
}
__device__ __forceinline__ void mma16816h(float* c, const uint32_t* a, const uint32_t* b) {
    asm volatile("mma.sync.aligned.m16n8k16.row.col.f32.f16.f16.f32 "
        "{%0,%1,%2,%3}, {%4,%5,%6,%7}, {%8,%9}, {%0,%1,%2,%3};"
        : "+f"(c[0]), "+f"(c[1]), "+f"(c[2]), "+f"(c[3])
        : "r"(a[0]), "r"(a[1]), "r"(a[2]), "r"(a[3]), "r"(b[0]), "r"(b[1]));
}

// ---------------- mask dtype detection + packing ----------------------------------
__global__ void detect_mask_kernel(const void* m) {
    __shared__ int cu, ci, cf;
    if (threadIdx.x == 0) { cu = 0; ci = 0; cf = 0; }
    __syncthreads();
    const unsigned char* u8 = (const unsigned char*)m;
    const int*   i32 = (const int*)m;
    const float* f32 = (const float*)m;
    int lu = 0;
    for (int i = threadIdx.x; i < SEQ; i += 256)
        if (u8[(size_t)i*(SEQ+1)]) lu++;
    atomicAdd(&cu, lu);
    if (threadIdx.x < 250) {
        if (i32[(size_t)threadIdx.x*(SEQ+1)] != 0)    atomicAdd(&ci, 1);
        if (f32[(size_t)threadIdx.x*(SEQ+1)] == 1.0f) atomicAdd(&cf, 1);
    }
    __syncthreads();
    if (threadIdx.x == 0)
        g_mask_mode = (cu == SEQ) ? 0 : (cf == 250) ? 2 : (ci == 250) ? 1 : 0;
}

__global__ void pack_mask_kernel(const void* m) {
    int w = blockIdx.x * blockDim.x + threadIdx.x;
    if (w >= SEQ*SEQ/32) return;
    int mode = g_mask_mode;
    size_t base = (size_t)w * 32;
    unsigned out = 0;
    if (mode == 0) {
        const unsigned char* p = (const unsigned char*)m;
        #pragma unroll
        for (int j = 0; j < 32; j++) if (p[base+j]) out |= 1u << j;
    } else if (mode == 1) {
        const int* p = (const int*)m;
        #pragma unroll
        for (int j = 0; j < 32; j++) if (p[base+j] != 0) out |= 1u << j;
    } else {
        const float* p = (const float*)m;
        #pragma unroll
        for (int j = 0; j < 32; j++) if (p[base+j] != 0.0f) out |= 1u << j;
    }
    g_maskbits[w] = out;
}

// ---------------- fp32 -> (hi, lo) fp16, row-major --------------------------------
__global__ __launch_bounds__(256) void convert_hilo_h_kernel(
    const float* __restrict__ src, __half* __restrict__ hi,
    __half* __restrict__ lo, int n4)
{
    int t = blockIdx.x * 256 + threadIdx.x;
    if (t >= n4) return;
    float4 v = *(const float4*)(src + (size_t)t * 4);
    float a[4] = {v.x, v.y, v.z, v.w};
    __half h[4], l[4];
    #pragma unroll
    for (int j = 0; j < 4; j++) {
        h[j] = __float2half(a[j]);
        l[j] = __float2half(a[j] - __half2float(h[j]));
    }
    *(uint2*)(hi + (size_t)t * 4) = make_uint2(pk2h(h[0],h[1]), pk2h(h[2],h[3]));
    *(uint2*)(lo + (size_t)t * 4) = make_uint2(pk2h(l[0],l[1]), pk2h(l[2],l[3]));
}

// fp32 -> fp16 hi only
__global__ __launch_bounds__(256) void convert_h_kernel(
    const float* __restrict__ src, __half* __restrict__ hi, int n4)
{
    int t = blockIdx.x * 256 + threadIdx.x;
    if (t >= n4) return;
    float4 v = *(const float4*)(src + (size_t)t * 4);
    *(uint2*)(hi + (size_t)t * 4) = make_uint2(
        pk2h(__float2half(v.x), __float2half(v.y)),
        pk2h(__float2half(v.z), __float2half(v.w)));
}

// fp32 -> fp16 hi ONLY, 4 weights (blockIdx.y selects)
__global__ __launch_bounds__(256) void convert_w4_kernel(
    const float* w0, const float* w1, const float* w2, const float* w3, int n4)
{
    int t = blockIdx.x * 256 + threadIdx.x;
    if (t >= n4) return;
    int z = blockIdx.y;
    const float* src = (z == 0) ? w0 : (z == 1) ? w1 : (z == 2) ? w2 : w3;
    __half* hi = g_w_hi[z];
    float4 v = *(const float4*)(src + (size_t)t * 4);
    *(uint2*)(hi + (size_t)t * 4) = make_uint2(
        pk2h(__float2half(v.x), __float2half(v.y)),
        pk2h(__float2half(v.z), __float2half(v.w)));
}

// ---------------- split-fp16 HMMA GEMM (R11, passed) ------------------------------
#define GS_ROW   24
#define GS_ARR   (128*GS_ROW*2)            // 6144 B per array
#define GS_BUF   (3*GS_ARR)                // 18432 B per stage
#define GS_TOTAL (2*GS_BUF)                // 36864 B

__global__ __launch_bounds__(256, 2) void gemm_hmma_kernel(
    const __half* __restrict__ ahi, const __half* __restrict__ alo,
    const __half* w0h, float* c0,
    const __half* w1h, float* c1,
    const __half* w2h, float* c2)
{
    extern __shared__ char sm[];
    uint32_t sb = smem_u32(sm);
    int tid = threadIdx.x, wid = tid >> 5, lane = tid & 31;
    int bn0 = blockIdx.x * 128, bm0 = blockIdx.y * 128, z = blockIdx.z;
    const __half* wh = (z == 0) ? w0h : (z == 1) ? w1h : w2h;
    float* C = (z == 0) ? c0 : (z == 1) ? c1 : c2;

    int wm = wid >> 1, wn = wid & 1;

    int lrow = tid >> 1, lhalf = tid & 1;
    const __half* gA_hi = ahi + (size_t)(bm0 + lrow) * DIM + lhalf * 8;
    const __half* gA_lo = alo + (size_t)(bm0 + lrow) * DIM + lhalf * 8;
    const __half* gB_hi = wh  + (size_t)(bn0 + lrow) * DIM + lhalf * 8;
    uint32_t sOff = (uint32_t)(lrow * GS_ROW + lhalf * 8) * 2;

    float acc[2][8][4];
    #pragma unroll
    for (int i = 0; i < 2; i++)
        #pragma unroll
        for (int j = 0; j < 8; j++)
            #pragma unroll
            for (int r = 0; r < 4; r++) acc[i][j][r] = 0.0f;

    uint32_t aRowByte = (uint32_t)((wm*32 + (lane & 15)) * GS_ROW + (lane >> 4) * 8) * 2;
    uint32_t bRowByte = (uint32_t)((wn*64 + ((lane >> 4) & 1)*8 + (lane & 7)) * GS_ROW
                                   + ((lane >> 3) & 1) * 8) * 2;

    {
        uint32_t s0 = sb + sOff;
        cp16(s0,            gA_hi);
        cp16(s0 + GS_ARR,   gA_lo);
        cp16(s0 + 2*GS_ARR, gB_hi);
        asm volatile("cp.async.commit_group;");
    }

    for (int ks = 0; ks < 64; ks++) {
        int cur = ks & 1;
        if (ks < 63) {
            uint32_t s0 = sb + (cur ^ 1) * GS_BUF + sOff;
            int k0 = (ks + 1) * 16;
            cp16(s0,            gA_hi + k0);
            cp16(s0 + GS_ARR,   gA_lo + k0);
            cp16(s0 + 2*GS_ARR, gB_hi + k0);
            asm volatile("cp.async.commit_group;");
            asm volatile("cp.async.wait_group 1;");
        } else {
            asm volatile("cp.async.wait_group 0;");
        }
        __syncthreads();

        uint32_t bufb = sb + cur * GS_BUF;

        uint32_t ah[2][4], al[2][4];
        #pragma unroll
        for (int mf = 0; mf < 2; mf++) {
            uint32_t addr = bufb + aRowByte + (uint32_t)(mf * 16 * GS_ROW) * 2;
            ldm_x4(ah[mf], addr);
            ldm_x4(al[mf], addr + GS_ARR);
        }
        #pragma unroll
        for (int pr = 0; pr < 4; pr++) {
            uint32_t bhv[4];
            uint32_t addr = bufb + 2*GS_ARR + bRowByte + (uint32_t)(pr * 16 * GS_ROW) * 2;
            ldm_x4(bhv, addr);
            #pragma unroll
            for (int mf = 0; mf < 2; mf++) {
                mma16816h(acc[mf][2*pr],   ah[mf], bhv);
                mma16816h(acc[mf][2*pr+1], ah[mf], bhv+2);
            }
            #pragma unroll
            for (int mf = 0; mf < 2; mf++) {
                mma16816h(acc[mf][2*pr],   al[mf], bhv);
                mma16816h(acc[mf][2*pr+1], al[mf], bhv+2);
            }
        }
        __syncthreads();
    }

    int gid4 = lane >> 2, l4 = lane & 3;
    #pragma unroll
    for (int mf = 0; mf < 2; mf++) {
        int row = bm0 + wm*32 + mf*16 + gid4;
        #pragma unroll
        for (int nf = 0; nf < 8; nf++) {
            int col = bn0 + wn*64 + nf*8 + l4*2;
            *(float2*)(C + (size_t)row * DIM + col) =
                make_float2(acc[mf][nf][0], acc[mf][nf][1]);
            *(float2*)(C + (size_t)(row + 8) * DIM + col) =
                make_float2(acc[mf][nf][2], acc[mf][nf][3]);
        }
    }
}

// ---------------- QKNorm + RoPE -> fp16 Q hi/lo, K hi -----------------------------
__global__ __launch_bounds__(256) void norm_rope_kernel(
    const float* __restrict__ qg, const float* __restrict__ kg,
    const float* __restrict__ cosb, const float* __restrict__ sinb,
    const int* __restrict__ ridx)
{
    int task = blockIdx.x * 8 + (threadIdx.x >> 5);
    int t = threadIdx.x & 31;
    int which = task >> 17;
    int rem = task & 0x1FFFF;
    int head = rem & (NHEAD - 1);
    int tok  = rem >> 4;
    const float* base = (which ? g_k : g_q) + (size_t)tok * DIM + head * HDIM;
    const float* gamma = which ? kg : qg;
    float x0 = base[t], x1 = base[t + 32];
    float ss = x0*x0 + x1*x1;
    #pragma unroll
    for (int off = 16; off >= 1; off >>= 1)
        ss += __shfl_xor_sync(0xffffffffu, ss, off);
    float r = rsqrtf(ss * (1.0f/64.0f) + EPSN);
    float n0 = x0 * r * gamma[t];
    float n1 = x1 * r * gamma[t + 32];
    int idx = ridx[tok & (SEQ - 1)];
    if (idx >= 0) {
        const float* cp = cosb + (size_t)idx * HDIM;
        const float* sp = sinb + (size_t)idx * HDIM;
        float o0 = n0 * cp[t]      - n1 * sp[t];
        float o1 = n1 * cp[t + 32] + n0 * sp[t + 32];
        n0 = o0; n1 = o1;
    }
    __half h0 = __float2half(n0), h1 = __float2half(n1);
    if (which) {                       // K: hi only
        __half* dh = g_kbh + (size_t)tok * DIM + head * HDIM;
        dh[t] = h0; dh[t + 32] = h1;
    } else {                           // Q: hi + lo
        __half* dh = g_qbh + (size_t)tok * DIM + head * HDIM;
        __half* dl = g_qbl + (size_t)tok * DIM + head * HDIM;
        dh[t] = h0; dh[t + 32] = h1;
        dl[t]      = __float2half(n0 - __half2float(h0));
        dl[t + 32] = __float2half(n1 - __half2float(h1));
    }
}

// ---------------- tensor-core flash attention, fp16 2-product ---------------------
// S = (Qhi+Qlo)·Khi ; O = (Phi+Plo)·Vhi. K and V are hi-only -> half smem/traffic.
#define A_STR   144
#define A_QH    0
#define A_QL    (128*A_STR)
#define A_ST0   (2*128*A_STR)               // 36864
#define A_KH    0
#define A_VH    18432
#define A_STAGE 36864
#define A_SMEM  (A_ST0 + 2*A_STAGE)         // 110592

__global__ __launch_bounds__(256, 1) void attn_tc_kernel() {
    extern __shared__ char smc[];
    uint32_t sb = smem_u32(smc);
    int tid = threadIdx.x, wid = tid >> 5, lane = tid & 31;
    int qt = blockIdx.x, h = blockIdx.y, b = blockIdx.z;
    int gid4 = lane >> 2, l4 = lane & 3;

    size_t qtok0 = (size_t)(b*SEQ + qt*128);

    #pragma unroll
    for (int i = 0; i < 4; i++) {
        int id = tid + i*256;
        int r = id >> 3, ch = id & 7;
        size_t gq = (qtok0 + r) * DIM + h*HDIM + ch*8;
        cp16(sb + A_QH + r*A_STR + ch*16, g_qbh + gq);
        cp16(sb + A_QL + r*A_STR + ch*16, g_qbl + gq);
        size_t gk = ((size_t)(b*SEQ + r)) * DIM + h*HDIM + ch*8;
        uint32_t st = sb + A_ST0;
        cp16(st + A_KH + r*A_STR + ch*16, g_kbh + gk);
        cp16(st + A_VH + r*A_STR + ch*16, g_vbh + gk);
    }
    asm volatile("cp.async.commit_group;");
    asm volatile("cp.async.wait_group 0;");
    __syncthreads();

    uint32_t qfh[4][4], qfl[4][4];
    {
        uint32_t arow = (uint32_t)(wid*16 + (lane & 15));
        uint32_t acol = (uint32_t)((lane >> 4) * 16);
        #pragma unroll
        for (int ks = 0; ks < 4; ks++) {
            ldm_x4(qfh[ks], sb + A_QH + arow*A_STR + ks*32 + acol);
            ldm_x4(qfl[ks], sb + A_QL + arow*A_STR + ks*32 + acol);
        }
    }

    float o[8][4];
    #pragma unroll
    for (int i = 0; i < 8; i++)
        #pragma unroll
        for (int j = 0; j < 4; j++) o[i][j] = 0.0f;
    float m0 = NEGINF, m1 = NEGINF, l0 = 0.0f, l1 = 0.0f;

    int qr0 = qt*128 + wid*16 + gid4;
    uint32_t brow = (uint32_t)(((lane >> 4) & 1)*8 + (lane & 7));
    uint32_t bcol = (uint32_t)(((lane >> 3) & 1) * 16);
    uint32_t vrow = (uint32_t)(((lane >> 3) & 1)*8 + (lane & 7));
    uint32_t vcol = (uint32_t)((lane >> 4) * 16);

    for (int kt = 0; kt < 8; kt++) {
        uint32_t st = sb + A_ST0 + (uint32_t)(kt & 1)*A_STAGE;
        if (kt < 7) {
            uint32_t sn = sb + A_ST0 + (uint32_t)((kt+1) & 1)*A_STAGE;
            #pragma unroll
            for (int i = 0; i < 4; i++) {
                int id = tid + i*256;
                int r = id >> 3, ch = id & 7;
                size_t g = ((size_t)(b*SEQ + (kt+1)*128 + r)) * DIM + h*HDIM + ch*8;
                cp16(sn + A_KH + r*A_STR + ch*16, g_kbh + g);
                cp16(sn + A_VH + r*A_STR + ch*16, g_vbh + g);
            }
            asm volatile("cp.async.commit_group;");
            asm volatile("cp.async.wait_group 1;");
        } else {
            asm volatile("cp.async.wait_group 0;");
        }
        __syncthreads();

        // ---- S = Q Khi^T (2 products) ----
        float c[16][4];
        #pragma unroll
        for (int i = 0; i < 16; i++)
            #pragma unroll
            for (int j = 0; j < 4; j++) c[i][j] = 0.0f;
        #pragma unroll
        for (int ks = 0; ks < 4; ks++) {
            #pragma unroll
            for (int np = 0; np < 8; np++) {
                uint32_t kb[4];
                uint32_t off = (uint32_t)(np*16 + brow)*A_STR + ks*32 + bcol;
                ldm_x4(kb, st + A_KH + off);
                mma16816h(c[2*np],   qfh[ks], kb);
                mma16816h(c[2*np+1], qfh[ks], kb+2);
                mma16816h(c[2*np],   qfl[ks], kb);
                mma16816h(c[2*np+1], qfl[ks], kb+2);
            }
        }

        unsigned w0[4], w1[4];
        #pragma unroll
        for (int w = 0; w < 4; w++) {
            w0[w] = g_maskbits[qr0*32 + kt*4 + w];
            w1[w] = g_maskbits[(qr0+8)*32 + kt*4 + w];
        }
        float tm0 = NEGINF, tm1 = NEGINF;
        #pragma unroll
        for (int nf = 0; nf < 16; nf++) {
            int word = nf >> 2;
            int bit = (nf & 3)*8 + l4*2;
            #pragma unroll
            for (int e = 0; e < 4; e++) {
                float y  = c[nf][e] * (SCALE / CAP);
                float y2 = y * y;
                float a  = CAP * (y * (1.0f + y2 * (-0.3333333433f + y2 * 0.1333333403f)));
                unsigned wv = (e < 2) ? w0[word] : w1[word];
                c[nf][e] = ((wv >> (bit + (e & 1))) & 1u) ? a : NEGINF;
            }
            tm0 = fmaxf(tm0, fmaxf(c[nf][0], c[nf][1]));
            tm1 = fmaxf(tm1, fmaxf(c[nf][2], c[nf][3]));
        }
        tm0 = fmaxf(tm0, __shfl_xor_sync(0xffffffffu, tm0, 1));
        tm0 = fmaxf(tm0, __shfl_xor_sync(0xffffffffu, tm0, 2));
        tm1 = fmaxf(tm1, __shfl_xor_sync(0xffffffffu, tm1, 1));
        tm1 = fmaxf(tm1, __shfl_xor_sync(0xffffffffu, tm1, 2));
        float mn0 = fmaxf(m0, tm0), mn1 = fmaxf(m1, tm1);
        float al0 = __expf(m0 - mn0), al1 = __expf(m1 - mn1);
        m0 = mn0; m1 = mn1;
        float rs0 = 0.0f, rs1 = 0.0f;
        #pragma unroll
        for (int nf = 0; nf < 16; nf++) {
            c[nf][0] = __expf(c[nf][0] - mn0);
            c[nf][1] = __expf(c[nf][1] - mn0);
            c[nf][2] = __expf(c[nf][2] - mn1);
            c[nf][3] = __expf(c[nf][3] - mn1);
            rs0 += c[nf][0] + c[nf][1];
            rs1 += c[nf][2] + c[nf][3];
        }
        rs0 += __shfl_xor_sync(0xffffffffu, rs0, 1);
        rs0 += __shfl_xor_sync(0xffffffffu, rs0, 2);
        rs1 += __shfl_xor_sync(0xffffffffu, rs1, 1);
        rs1 += __shfl_xor_sync(0xffffffffu, rs1, 2);
        l0 = l0 * al0 + rs0;
        l1 = l1 * al1 + rs1;
        #pragma unroll
        for (int nf = 0; nf < 8; nf++) {
            o[nf][0] *= al0; o[nf][1] *= al0; o[nf][2] *= al1; o[nf][3] *= al1;
        }

        // ---- O += P Vhi (2 products; P split in fp16) ----
        #pragma unroll
        for (int ks = 0; ks < 8; ks++) {
            uint32_t pah[4], pal[4];
            pksplit_h(c[2*ks][0],   c[2*ks][1],   pah[0], pal[0]);
            pksplit_h(c[2*ks][2],   c[2*ks][3],   pah[1], pal[1]);
            pksplit_h(c[2*ks+1][0], c[2*ks+1][1], pah[2], pal[2]);
            pksplit_h(c[2*ks+1][2], c[2*ks+1][3], pah[3], pal[3]);
            #pragma unroll
            for (int npv = 0; npv < 4; npv++) {
                uint32_t vb[4];
                uint32_t off = (uint32_t)(ks*16 + vrow)*A_STR + npv*32 + vcol;
                ldm_x4_t(vb, st + A_VH + off);
                mma16816h(o[2*npv],   pah, vb);
                mma16816h(o[2*npv+1], pah, vb+2);
                mma16816h(o[2*npv],   pal, vb);
                mma16816h(o[2*npv+1], pal, vb+2);
            }
        }
        __syncthreads();
    }

    // epilogue: normalize, write (hi, lo) fp16 for the O projection
    float inv0 = 1.0f / l0, inv1 = 1.0f / l1;
    size_t r0g = (qtok0 + wid*16 + gid4) * DIM + h*HDIM;
    size_t r1g = r0g + (size_t)8 * DIM;
    #pragma unroll
    for (int nf = 0; nf < 8; nf++) {
        int col = nf*8 + l4*2;
        uint32_t hi0, lo0, hi1, lo1;
        pksplit_h(o[nf][0]*inv0, o[nf][1]*inv0, hi0, lo0);
        pksplit_h(o[nf][2]*inv1, o[nf][3]*inv1, hi1, lo1);
        *(uint32_t*)(g_att_hi + r0g + col) = hi0;
        *(uint32_t*)(g_att_lo + r0g + col) = lo0;
        *(uint32_t*)(g_att_hi + r1g + col) = hi1;
        *(uint32_t*)(g_att_lo + r1g + col) = lo1;
    }
}

// ---------------- launch ----------------------------------------------------------
extern "C" void kernel_launch(void* const* d_in, const int* in_sizes, int n_in,
                              void* d_out, int out_size)
{
    const float* x    = (const float*)d_in[0];
    const float* Wq   = (const float*)d_in[1];
    const float* Wk   = (const float*)d_in[2];
    const float* Wv   = (const float*)d_in[3];
    const float* Wo   = (const float*)d_in[4];
    const float* qg   = (const float*)d_in[5];
    const float* kg   = (const float*)d_in[6];
    const float* cosb = (const float*)d_in[7];
    const float* sinb = (const float*)d_in[8];
    const int*   ridx = (const int*)d_in[9];
    const void*  mask = d_in[10];
    float* out = (float*)d_out;

    float *gq, *gk, *gv;
    __half *xhi, *xlo, *athi, *atlo, *whB, *vbh;
    cudaGetSymbolAddress((void**)&gq,   g_q);
    cudaGetSymbolAddress((void**)&gk,   g_k);
    cudaGetSymbolAddress((void**)&gv,   g_v);
    cudaGetSymbolAddress((void**)&xhi,  g_x_hi);
    cudaGetSymbolAddress((void**)&xlo,  g_x_lo);
    cudaGetSymbolAddress((void**)&athi, g_att_hi);
    cudaGetSymbolAddress((void**)&atlo, g_att_lo);
    cudaGetSymbolAddress((void**)&whB,  g_w_hi);
    cudaGetSymbolAddress((void**)&vbh,  g_vbh);
    __half *wqh = whB;
    __half *wkh = whB + 1*DIM*DIM;
    __half *wvh = whB + 2*DIM*DIM;
    __half *woh = whB + 3*DIM*DIM;

    cudaFuncSetAttribute(gemm_hmma_kernel,
        cudaFuncAttributeMaxDynamicSharedMemorySize, GS_TOTAL);
    cudaFuncSetAttribute(attn_tc_kernel,
        cudaFuncAttributeMaxDynamicSharedMemorySize, A_SMEM);

    // QKV GEMM kept at launch position 4 for ncu capture.
    detect_mask_kernel<<<1, 256>>>(mask);                                            // 1
    convert_hilo_h_kernel<<<(MTOT*DIM/4 + 255)/256, 256>>>(x, xhi, xlo, MTOT*DIM/4); // 2
    convert_w4_kernel<<<dim3((DIM*DIM/4 + 255)/256, 4), 256>>>(                      // 3
        Wq, Wk, Wv, Wo, DIM*DIM/4);

    gemm_hmma_kernel<<<dim3(8, 64, 3), 256, GS_TOTAL>>>(                             // 4 (QKV)
        xhi, xlo, wqh, gq, wkh, gk, wvh, gv);

    pack_mask_kernel<<<(SEQ*SEQ/32 + 255)/256, 256>>>(mask);                         // 5
    norm_rope_kernel<<<(2*MTOT*NHEAD)/8, 256>>>(qg, kg, cosb, sinb, ridx);           // 6
    convert_h_kernel<<<(MTOT*DIM/4 + 255)/256, 256>>>(gv, vbh, MTOT*DIM/4);          // 7

    attn_tc_kernel<<<dim3(SEQ/128, NHEAD, BATCH), 256, A_SMEM>>>();                  // 8

    gemm_hmma_kernel<<<dim3(8, 64, 1), 256, GS_TOTAL>>>(                             // 9 (O)
        athi, atlo, woh, out, woh, out, woh, out);
}

// round 14
// speedup vs baseline: 1.5983x; 1.1014x over previous
#include <cuda_runtime.h>
#include <cuda_bf16.h>
#include <cuda_fp16.h>
#include <math.h>
#include <stdint.h>

#define BATCH 8
#define SEQ   1024
#define DIM   1024
#define NHEAD 16
#define HDIM  64
#define MTOT  (BATCH*SEQ)           // 8192 tokens
#define SCALE 0.125f                // HD^-0.5
#define CAP   50.0f
#define EPSN  1e-6f
#define NEGINF (-1e30f)

// ---------------- scratch (device globals: no allocation allowed) ----------------
__device__ float g_q[MTOT*DIM];
__device__ float g_k[MTOT*DIM];
// fp16 hi/lo operands for projection GEMMs (W needs hi only)
__device__ __half g_x_hi[MTOT*DIM];
__device__ __half g_x_lo[MTOT*DIM];
__device__ __half g_att_hi[MTOT*DIM];
__device__ __half g_att_lo[MTOT*DIM];
__device__ __half g_w_hi[4][DIM*DIM];          // q,k,v,o
// fp16 operands for tensor-core attention: Q hi, K hi, V hi (pure fp16)
__device__ __half g_qbh[MTOT*DIM];
__device__ __half g_kbh[MTOT*DIM];
__device__ __half g_vbh[MTOT*DIM];
__device__ unsigned g_maskbits[SEQ*(SEQ/32)];
__device__ int g_mask_mode;

__device__ __forceinline__ uint32_t smem_u32(const void* p) {
    uint32_t a;
    asm("{ .reg .u64 t; cvta.to.shared.u64 t, %1; cvt.u32.u64 %0, t; }" : "=r"(a) : "l"(p));
    return a;
}
__device__ __forceinline__ unsigned pk2h(__half a, __half b) {
    return (unsigned)__half_as_ushort(a) | ((unsigned)__half_as_ushort(b) << 16);
}
__device__ __forceinline__ void pksplit_h(float x, float y, uint32_t& hi, uint32_t& lo) {
    __half hx = __float2half(x), hy = __float2half(y);
    hi = pk2h(hx, hy);
    lo = pk2h(__float2half(x - __half2float(hx)),
              __float2half(y - __half2float(hy)));
}
__device__ __forceinline__ void cp16(uint32_t s, const void* g) {
    asm volatile("cp.async.cg.shared.global [%0], [%1], 16;" :: "r"(s), "l"(g));
}
__device__ __forceinline__ void ldm_x4(uint32_t* r, uint32_t a) {
    asm volatile("ldmatrix.sync.aligned.m8n8.x4.shared.b16 {%0,%1,%2,%3}, [%4];"
        : "=r"(r[0]), "=r"(r[1]), "=r"(r[2]), "=r"(r[3]) : "r"(a));
}
__device__ __forceinline__ void ldm_x4_t(uint32_t* r, uint32_t a) {
    asm volatile("ldmatrix.sync.aligned.m8n8.x4.trans.shared.b16 {%0,%1,%2,%3}, [%4];"
        : "=r"(r[0]), "=r"(r[1]), "=r"(r[2]), "=r"(r[3]) : "r"(a));
}
__device__ __forceinline__ void mma16816h(float* c, const uint32_t* a, const uint32_t* b) {
    asm volatile("mma.sync.aligned.m16n8k16.row.col.f32.f16.f16.f32 "
        "{%0,%1,%2,%3}, {%4,%5,%6,%7}, {%8,%9}, {%0,%1,%2,%3};"
        : "+f"(c[0]), "+f"(c[1]), "+f"(c[2]), "+f"(c[3])
        : "r"(a[0]), "r"(a[1]), "r"(a[2]), "r"(a[3]), "r"(b[0]), "r"(b[1]));
}

// ---------------- mask dtype detection + packing ----------------------------------
__global__ void detect_mask_kernel(const void* m) {
    __shared__ int cu, ci, cf;
    if (threadIdx.x == 0) { cu = 0; ci = 0; cf = 0; }
    __syncthreads();
    const unsigned char* u8 = (const unsigned char*)m;
    const int*   i32 = (const int*)m;
    const float* f32 = (const float*)m;
    int lu = 0;
    for (int i = threadIdx.x; i < SEQ; i += 256)
        if (u8[(size_t)i*(SEQ+1)]) lu++;
    atomicAdd(&cu, lu);
    if (threadIdx.x < 250) {
        if (i32[(size_t)threadIdx.x*(SEQ+1)] != 0)    atomicAdd(&ci, 1);
        if (f32[(size_t)threadIdx.x*(SEQ+1)] == 1.0f) atomicAdd(&cf, 1);
    }
    __syncthreads();
    if (threadIdx.x == 0)
        g_mask_mode = (cu == SEQ) ? 0 : (cf == 250) ? 2 : (ci == 250) ? 1 : 0;
}

__global__ void pack_mask_kernel(const void* m) {
    int w = blockIdx.x * blockDim.x + threadIdx.x;
    if (w >= SEQ*SEQ/32) return;
    int mode = g_mask_mode;
    size_t base = (size_t)w * 32;
    unsigned out = 0;
    if (mode == 0) {
        const unsigned char* p = (const unsigned char*)m;
        #pragma unroll
        for (int j = 0; j < 32; j++) if (p[base+j]) out |= 1u << j;
    } else if (mode == 1) {
        const int* p = (const int*)m;
        #pragma unroll
        for (int j = 0; j < 32; j++) if (p[base+j] != 0) out |= 1u << j;
    } else {
        const float* p = (const float*)m;
        #pragma unroll
        for (int j = 0; j < 32; j++) if (p[base+j] != 0.0f) out |= 1u << j;
    }
    g_maskbits[w] = out;
}

// ---------------- fp32 -> (hi, lo) fp16, row-major --------------------------------
__global__ __launch_bounds__(256) void convert_hilo_h_kernel(
    const float* __restrict__ src, __half* __restrict__ hi,
    __half* __restrict__ lo, int n4)
{
    int t = blockIdx.x * 256 + threadIdx.x;
    if (t >= n4) return;
    float4 v = *(const float4*)(src + (size_t)t * 4);
    float a[4] = {v.x, v.y, v.z, v.w};
    __half h[4], l[4];
    #pragma unroll
    for (int j = 0; j < 4; j++) {
        h[j] = __float2half(a[j]);
        l[j] = __float2half(a[j] - __half2float(h[j]));
    }
    *(uint2*)(hi + (size_t)t * 4) = make_uint2(pk2h(h[0],h[1]), pk2h(h[2],h[3]));
    *(uint2*)(lo + (size_t)t * 4) = make_uint2(pk2h(l[0],l[1]), pk2h(l[2],l[3]));
}

// fp32 -> fp16 hi ONLY, 4 weights (blockIdx.y selects)
__global__ __launch_bounds__(256) void convert_w4_kernel(
    const float* w0, const float* w1, const float* w2, const float* w3, int n4)
{
    int t = blockIdx.x * 256 + threadIdx.x;
    if (t >= n4) return;
    int z = blockIdx.y;
    const float* src = (z == 0) ? w0 : (z == 1) ? w1 : (z == 2) ? w2 : w3;
    __half* hi = g_w_hi[z];
    float4 v = *(const float4*)(src + (size_t)t * 4);
    *(uint2*)(hi + (size_t)t * 4) = make_uint2(
        pk2h(__float2half(v.x), __float2half(v.y)),
        pk2h(__float2half(v.z), __float2half(v.w)));
}

// ---------------- split-fp16 HMMA GEMM: C = (Ahi+Alo)·Whi -------------------------
// z==2 with half_out: epilogue writes fp16 directly (V path -> g_vbh), skipping
// the fp32 round-trip + separate convert kernel.
#define GS_ROW   24
#define GS_ARR   (128*GS_ROW*2)            // 6144 B per array
#define GS_BUF   (3*GS_ARR)                // 18432 B per stage
#define GS_TOTAL (2*GS_BUF)                // 36864 B

__global__ __launch_bounds__(256, 2) void gemm_hmma_kernel(
    const __half* __restrict__ ahi, const __half* __restrict__ alo,
    const __half* w0h, float* c0,
    const __half* w1h, float* c1,
    const __half* w2h, __half* c2h)
{
    extern __shared__ char sm[];
    uint32_t sb = smem_u32(sm);
    int tid = threadIdx.x, wid = tid >> 5, lane = tid & 31;
    int bn0 = blockIdx.x * 128, bm0 = blockIdx.y * 128, z = blockIdx.z;
    const __half* wh = (z == 0) ? w0h : (z == 1) ? w1h : w2h;

    int wm = wid >> 1, wn = wid & 1;

    int lrow = tid >> 1, lhalf = tid & 1;
    const __half* gA_hi = ahi + (size_t)(bm0 + lrow) * DIM + lhalf * 8;
    const __half* gA_lo = alo + (size_t)(bm0 + lrow) * DIM + lhalf * 8;
    const __half* gB_hi = wh  + (size_t)(bn0 + lrow) * DIM + lhalf * 8;
    uint32_t sOff = (uint32_t)(lrow * GS_ROW + lhalf * 8) * 2;

    float acc[2][8][4];
    #pragma unroll
    for (int i = 0; i < 2; i++)
        #pragma unroll
        for (int j = 0; j < 8; j++)
            #pragma unroll
            for (int r = 0; r < 4; r++) acc[i][j][r] = 0.0f;

    uint32_t aRowByte = (uint32_t)((wm*32 + (lane & 15)) * GS_ROW + (lane >> 4) * 8) * 2;
    uint32_t bRowByte = (uint32_t)((wn*64 + ((lane >> 4) & 1)*8 + (lane & 7)) * GS_ROW
                                   + ((lane >> 3) & 1) * 8) * 2;

    {
        uint32_t s0 = sb + sOff;
        cp16(s0,            gA_hi);
        cp16(s0 + GS_ARR,   gA_lo);
        cp16(s0 + 2*GS_ARR, gB_hi);
        asm volatile("cp.async.commit_group;");
    }

    for (int ks = 0; ks < 64; ks++) {
        int cur = ks & 1;
        if (ks < 63) {
            uint32_t s0 = sb + (cur ^ 1) * GS_BUF + sOff;
            int k0 = (ks + 1) * 16;
            cp16(s0,            gA_hi + k0);
            cp16(s0 + GS_ARR,   gA_lo + k0);
            cp16(s0 + 2*GS_ARR, gB_hi + k0);
            asm volatile("cp.async.commit_group;");
            asm volatile("cp.async.wait_group 1;");
        } else {
            asm volatile("cp.async.wait_group 0;");
        }
        __syncthreads();

        uint32_t bufb = sb + cur * GS_BUF;

        uint32_t ah[2][4], al[2][4];
        #pragma unroll
        for (int mf = 0; mf < 2; mf++) {
            uint32_t addr = bufb + aRowByte + (uint32_t)(mf * 16 * GS_ROW) * 2;
            ldm_x4(ah[mf], addr);
            ldm_x4(al[mf], addr + GS_ARR);
        }
        #pragma unroll
        for (int pr = 0; pr < 4; pr++) {
            uint32_t bhv[4];
            uint32_t addr = bufb + 2*GS_ARR + bRowByte + (uint32_t)(pr * 16 * GS_ROW) * 2;
            ldm_x4(bhv, addr);
            #pragma unroll
            for (int mf = 0; mf < 2; mf++) {
                mma16816h(acc[mf][2*pr],   ah[mf], bhv);
                mma16816h(acc[mf][2*pr+1], ah[mf], bhv+2);
            }
            #pragma unroll
            for (int mf = 0; mf < 2; mf++) {
                mma16816h(acc[mf][2*pr],   al[mf], bhv);
                mma16816h(acc[mf][2*pr+1], al[mf], bhv+2);
            }
        }
        __syncthreads();
    }

    int gid4 = lane >> 2, l4 = lane & 3;
    if (z == 2) {
        // V projection: write fp16 directly for the attention kernel
        #pragma unroll
        for (int mf = 0; mf < 2; mf++) {
            int row = bm0 + wm*32 + mf*16 + gid4;
            #pragma unroll
            for (int nf = 0; nf < 8; nf++) {
                int col = bn0 + wn*64 + nf*8 + l4*2;
                *(uint32_t*)(c2h + (size_t)row * DIM + col) =
                    pk2h(__float2half(acc[mf][nf][0]), __float2half(acc[mf][nf][1]));
                *(uint32_t*)(c2h + (size_t)(row + 8) * DIM + col) =
                    pk2h(__float2half(acc[mf][nf][2]), __float2half(acc[mf][nf][3]));
            }
        }
    } else {
        float* C = (z == 0) ? c0 : c1;
        #pragma unroll
        for (int mf = 0; mf < 2; mf++) {
            int row = bm0 + wm*32 + mf*16 + gid4;
            #pragma unroll
            for (int nf = 0; nf < 8; nf++) {
                int col = bn0 + wn*64 + nf*8 + l4*2;
                *(float2*)(C + (size_t)row * DIM + col) =
                    make_float2(acc[mf][nf][0], acc[mf][nf][1]);
                *(float2*)(C + (size_t)(row + 8) * DIM + col) =
                    make_float2(acc[mf][nf][2], acc[mf][nf][3]);
            }
        }
    }
}

// ---------------- QKNorm + RoPE -> fp16 hi (Q and K) ------------------------------
__global__ __launch_bounds__(256) void norm_rope_kernel(
    const float* __restrict__ qg, const float* __restrict__ kg,
    const float* __restrict__ cosb, const float* __restrict__ sinb,
    const int* __restrict__ ridx)
{
    int task = blockIdx.x * 8 + (threadIdx.x >> 5);
    int t = threadIdx.x & 31;
    int which = task >> 17;
    int rem = task & 0x1FFFF;
    int head = rem & (NHEAD - 1);
    int tok  = rem >> 4;
    const float* base = (which ? g_k : g_q) + (size_t)tok * DIM + head * HDIM;
    const float* gamma = which ? kg : qg;
    float x0 = base[t], x1 = base[t + 32];
    float ss = x0*x0 + x1*x1;
    #pragma unroll
    for (int off = 16; off >= 1; off >>= 1)
        ss += __shfl_xor_sync(0xffffffffu, ss, off);
    float r = rsqrtf(ss * (1.0f/64.0f) + EPSN);
    float n0 = x0 * r * gamma[t];
    float n1 = x1 * r * gamma[t + 32];
    int idx = ridx[tok & (SEQ - 1)];
    if (idx >= 0) {
        const float* cp = cosb + (size_t)idx * HDIM;
        const float* sp = sinb + (size_t)idx * HDIM;
        float o0 = n0 * cp[t]      - n1 * sp[t];
        float o1 = n1 * cp[t + 32] + n0 * sp[t + 32];
        n0 = o0; n1 = o1;
    }
    __half* dh = (which ? g_kbh : g_qbh) + (size_t)tok * DIM + head * HDIM;
    dh[t]      = __float2half(n0);
    dh[t + 32] = __float2half(n1);
}

// ---------------- tensor-core flash attention, pure fp16 --------------------------
// S = Qhi·Khi ; O = Phi·Vhi. Single product each -> half the MMAs of R12.
#define A_STR   144
#define A_QH    0
#define A_ST0   (128*A_STR)                 // 18432
#define A_KH    0
#define A_VH    18432
#define A_STAGE 36864
#define A_SMEM  (A_ST0 + 2*A_STAGE)         // 92160

__global__ __launch_bounds__(256, 1) void attn_tc_kernel() {
    extern __shared__ char smc[];
    uint32_t sb = smem_u32(smc);
    int tid = threadIdx.x, wid = tid >> 5, lane = tid & 31;
    int qt = blockIdx.x, h = blockIdx.y, b = blockIdx.z;
    int gid4 = lane >> 2, l4 = lane & 3;

    size_t qtok0 = (size_t)(b*SEQ + qt*128);

    #pragma unroll
    for (int i = 0; i < 4; i++) {
        int id = tid + i*256;
        int r = id >> 3, ch = id & 7;
        size_t gq = (qtok0 + r) * DIM + h*HDIM + ch*8;
        cp16(sb + A_QH + r*A_STR + ch*16, g_qbh + gq);
        size_t gk = ((size_t)(b*SEQ + r)) * DIM + h*HDIM + ch*8;
        uint32_t st = sb + A_ST0;
        cp16(st + A_KH + r*A_STR + ch*16, g_kbh + gk);
        cp16(st + A_VH + r*A_STR + ch*16, g_vbh + gk);
    }
    asm volatile("cp.async.commit_group;");
    asm volatile("cp.async.wait_group 0;");
    __syncthreads();

    uint32_t qfh[4][4];
    {
        uint32_t arow = (uint32_t)(wid*16 + (lane & 15));
        uint32_t acol = (uint32_t)((lane >> 4) * 16);
        #pragma unroll
        for (int ks = 0; ks < 4; ks++)
            ldm_x4(qfh[ks], sb + A_QH + arow*A_STR + ks*32 + acol);
    }

    float o[8][4];
    #pragma unroll
    for (int i = 0; i < 8; i++)
        #pragma unroll
        for (int j = 0; j < 4; j++) o[i][j] = 0.0f;
    float m0 = NEGINF, m1 = NEGINF, l0 = 0.0f, l1 = 0.0f;

    int qr0 = qt*128 + wid*16 + gid4;
    uint32_t brow = (uint32_t)(((lane >> 4) & 1)*8 + (lane & 7));
    uint32_t bcol = (uint32_t)(((lane >> 3) & 1) * 16);
    uint32_t vrow = (uint32_t)(((lane >> 3) & 1)*8 + (lane & 7));
    uint32_t vcol = (uint32_t)((lane >> 4) * 16);

    for (int kt = 0; kt < 8; kt++) {
        uint32_t st = sb + A_ST0 + (uint32_t)(kt & 1)*A_STAGE;
        if (kt < 7) {
            uint32_t sn = sb + A_ST0 + (uint32_t)((kt+1) & 1)*A_STAGE;
            #pragma unroll
            for (int i = 0; i < 4; i++) {
                int id = tid + i*256;
                int r = id >> 3, ch = id & 7;
                size_t g = ((size_t)(b*SEQ + (kt+1)*128 + r)) * DIM + h*HDIM + ch*8;
                cp16(sn + A_KH + r*A_STR + ch*16, g_kbh + g);
                cp16(sn + A_VH + r*A_STR + ch*16, g_vbh + g);
            }
            asm volatile("cp.async.commit_group;");
            asm volatile("cp.async.wait_group 1;");
        } else {
            asm volatile("cp.async.wait_group 0;");
        }
        __syncthreads();

        // ---- S = Qhi Khi^T (single product) ----
        float c[16][4];
        #pragma unroll
        for (int i = 0; i < 16; i++)
            #pragma unroll
            for (int j = 0; j < 4; j++) c[i][j] = 0.0f;
        #pragma unroll
        for (int ks = 0; ks < 4; ks++) {
            #pragma unroll
            for (int np = 0; np < 8; np++) {
                uint32_t kb[4];
                uint32_t off = (uint32_t)(np*16 + brow)*A_STR + ks*32 + bcol;
                ldm_x4(kb, st + A_KH + off);
                mma16816h(c[2*np],   qfh[ks], kb);
                mma16816h(c[2*np+1], qfh[ks], kb+2);
            }
        }

        unsigned w0[4], w1[4];
        #pragma unroll
        for (int w = 0; w < 4; w++) {
            w0[w] = g_maskbits[qr0*32 + kt*4 + w];
            w1[w] = g_maskbits[(qr0+8)*32 + kt*4 + w];
        }
        float tm0 = NEGINF, tm1 = NEGINF;
        #pragma unroll
        for (int nf = 0; nf < 16; nf++) {
            int word = nf >> 2;
            int bit = (nf & 3)*8 + l4*2;
            #pragma unroll
            for (int e = 0; e < 4; e++) {
                float y  = c[nf][e] * (SCALE / CAP);
                float y2 = y * y;
                float a  = CAP * (y * (1.0f + y2 * (-0.3333333433f + y2 * 0.1333333403f)));
                unsigned wv = (e < 2) ? w0[word] : w1[word];
                c[nf][e] = ((wv >> (bit + (e & 1))) & 1u) ? a : NEGINF;
            }
            tm0 = fmaxf(tm0, fmaxf(c[nf][0], c[nf][1]));
            tm1 = fmaxf(tm1, fmaxf(c[nf][2], c[nf][3]));
        }
        tm0 = fmaxf(tm0, __shfl_xor_sync(0xffffffffu, tm0, 1));
        tm0 = fmaxf(tm0, __shfl_xor_sync(0xffffffffu, tm0, 2));
        tm1 = fmaxf(tm1, __shfl_xor_sync(0xffffffffu, tm1, 1));
        tm1 = fmaxf(tm1, __shfl_xor_sync(0xffffffffu, tm1, 2));
        float mn0 = fmaxf(m0, tm0), mn1 = fmaxf(m1, tm1);
        float al0 = __expf(m0 - mn0), al1 = __expf(m1 - mn1);
        m0 = mn0; m1 = mn1;
        float rs0 = 0.0f, rs1 = 0.0f;
        #pragma unroll
        for (int nf = 0; nf < 16; nf++) {
            c[nf][0] = __expf(c[nf][0] - mn0);
            c[nf][1] = __expf(c[nf][1] - mn0);
            c[nf][2] = __expf(c[nf][2] - mn1);
            c[nf][3] = __expf(c[nf][3] - mn1);
            rs0 += c[nf][0] + c[nf][1];
            rs1 += c[nf][2] + c[nf][3];
        }
        rs0 += __shfl_xor_sync(0xffffffffu, rs0, 1);
        rs0 += __shfl_xor_sync(0xffffffffu, rs0, 2);
        rs1 += __shfl_xor_sync(0xffffffffu, rs1, 1);
        rs1 += __shfl_xor_sync(0xffffffffu, rs1, 2);
        l0 = l0 * al0 + rs0;
        l1 = l1 * al1 + rs1;
        #pragma unroll
        for (int nf = 0; nf < 8; nf++) {
            o[nf][0] *= al0; o[nf][1] *= al0; o[nf][2] *= al1; o[nf][3] *= al1;
        }

        // ---- O += Phi Vhi (single product) ----
        #pragma unroll
        for (int ks = 0; ks < 8; ks++) {
            uint32_t pah[4];
            pah[0] = pk2h(__float2half(c[2*ks][0]),   __float2half(c[2*ks][1]));
            pah[1] = pk2h(__float2half(c[2*ks][2]),   __float2half(c[2*ks][3]));
            pah[2] = pk2h(__float2half(c[2*ks+1][0]), __float2half(c[2*ks+1][1]));
            pah[3] = pk2h(__float2half(c[2*ks+1][2]), __float2half(c[2*ks+1][3]));
            #pragma unroll
            for (int npv = 0; npv < 4; npv++) {
                uint32_t vb[4];
                uint32_t off = (uint32_t)(ks*16 + vrow)*A_STR + npv*32 + vcol;
                ldm_x4_t(vb, st + A_VH + off);
                mma16816h(o[2*npv],   pah, vb);
                mma16816h(o[2*npv+1], pah, vb+2);
            }
        }
        __syncthreads();
    }

    // epilogue: normalize, write (hi, lo) fp16 for the O projection
    float inv0 = 1.0f / l0, inv1 = 1.0f / l1;
    size_t r0g = (qtok0 + wid*16 + gid4) * DIM + h*HDIM;
    size_t r1g = r0g + (size_t)8 * DIM;
    #pragma unroll
    for (int nf = 0; nf < 8; nf++) {
        int col = nf*8 + l4*2;
        uint32_t hi0, lo0, hi1, lo1;
        pksplit_h(o[nf][0]*inv0, o[nf][1]*inv0, hi0, lo0);
        pksplit_h(o[nf][2]*inv1, o[nf][3]*inv1, hi1, lo1);
        *(uint32_t*)(g_att_hi + r0g + col) = hi0;
        *(uint32_t*)(g_att_lo + r0g + col) = lo0;
        *(uint32_t*)(g_att_hi + r1g + col) = hi1;
        *(uint32_t*)(g_att_lo + r1g + col) = lo1;
    }
}

// ---------------- launch ----------------------------------------------------------
extern "C" void kernel_launch(void* const* d_in, const int* in_sizes, int n_in,
                              void* d_out, int out_size)
{
    const float* x    = (const float*)d_in[0];
    const float* Wq   = (const float*)d_in[1];
    const float* Wk   = (const float*)d_in[2];
    const float* Wv   = (const float*)d_in[3];
    const float* Wo   = (const float*)d_in[4];
    const float* qg   = (const float*)d_in[5];
    const float* kg   = (const float*)d_in[6];
    const float* cosb = (const float*)d_in[7];
    const float* sinb = (const float*)d_in[8];
    const int*   ridx = (const int*)d_in[9];
    const void*  mask = d_in[10];
    float* out = (float*)d_out;

    float *gq, *gk;
    __half *xhi, *xlo, *athi, *atlo, *whB, *vbh;
    cudaGetSymbolAddress((void**)&gq,   g_q);
    cudaGetSymbolAddress((void**)&gk,   g_k);
    cudaGetSymbolAddress((void**)&xhi,  g_x_hi);
    cudaGetSymbolAddress((void**)&xlo,  g_x_lo);
    cudaGetSymbolAddress((void**)&athi, g_att_hi);
    cudaGetSymbolAddress((void**)&atlo, g_att_lo);
    cudaGetSymbolAddress((void**)&whB,  g_w_hi);
    cudaGetSymbolAddress((void**)&vbh,  g_vbh);
    __half *wqh = whB;
    __half *wkh = whB + 1*DIM*DIM;
    __half *wvh = whB + 2*DIM*DIM;
    __half *woh = whB + 3*DIM*DIM;

    cudaFuncSetAttribute(gemm_hmma_kernel,
        cudaFuncAttributeMaxDynamicSharedMemorySize, GS_TOTAL);
    cudaFuncSetAttribute(attn_tc_kernel,
        cudaFuncAttributeMaxDynamicSharedMemorySize, A_SMEM);

    // QKV GEMM kept at launch position 4 for ncu capture.
    detect_mask_kernel<<<1, 256>>>(mask);                                            // 1
    convert_hilo_h_kernel<<<(MTOT*DIM/4 + 255)/256, 256>>>(x, xhi, xlo, MTOT*DIM/4); // 2
    convert_w4_kernel<<<dim3((DIM*DIM/4 + 255)/256, 4), 256>>>(                      // 3
        Wq, Wk, Wv, Wo, DIM*DIM/4);

    gemm_hmma_kernel<<<dim3(8, 64, 3), 256, GS_TOTAL>>>(                             // 4 (QKV; V->fp16)
        xhi, xlo, wqh, gq, wkh, gk, wvh, vbh);

    pack_mask_kernel<<<(SEQ*SEQ/32 + 255)/256, 256>>>(mask);                         // 5
    norm_rope_kernel<<<(2*MTOT*NHEAD)/8, 256>>>(qg, kg, cosb, sinb, ridx);           // 6

    attn_tc_kernel<<<dim3(SEQ/128, NHEAD, BATCH), 256, A_SMEM>>>();                  // 7

    gemm_hmma_kernel<<<dim3(8, 64, 1), 256, GS_TOTAL>>>(                             // 8 (O)
        athi, atlo, woh, out, woh, out, woh, (half*)out /*unused*/);
}

// round 15
// speedup vs baseline: 2.0649x; 1.2920x over previous
#include <cuda_runtime.h>
#include <cuda_bf16.h>
#include <cuda_fp16.h>
#include <math.h>
#include <stdint.h>

#define BATCH 8
#define SEQ   1024
#define DIM   1024
#define NHEAD 16
#define HDIM  64
#define MTOT  (BATCH*SEQ)           // 8192 tokens
#define SCALE 0.125f                // HD^-0.5
#define CAP   50.0f
#define EPSN  1e-6f
#define NEGINF (-1e30f)

// ---------------- scratch (device globals: no allocation allowed) ----------------
__device__ float g_q[MTOT*DIM];
__device__ float g_k[MTOT*DIM];
// fp16 operands (hi only everywhere now)
__device__ __half g_x_hi[MTOT*DIM];
__device__ __half g_att_hi[MTOT*DIM];
__device__ __half g_w_hi[4][DIM*DIM];          // q,k,v,o
__device__ __half g_qbh[MTOT*DIM];
__device__ __half g_kbh[MTOT*DIM];
__device__ __half g_vbh[MTOT*DIM];
__device__ unsigned g_maskbits[SEQ*(SEQ/32)];
__device__ int g_mask_mode;

__device__ __forceinline__ uint32_t smem_u32(const void* p) {
    uint32_t a;
    asm("{ .reg .u64 t; cvta.to.shared.u64 t, %1; cvt.u32.u64 %0, t; }" : "=r"(a) : "l"(p));
    return a;
}
__device__ __forceinline__ unsigned pk2h(__half a, __half b) {
    return (unsigned)__half_as_ushort(a) | ((unsigned)__half_as_ushort(b) << 16);
}
__device__ __forceinline__ void cp16(uint32_t s, const void* g) {
    asm volatile("cp.async.cg.shared.global [%0], [%1], 16;" :: "r"(s), "l"(g));
}
__device__ __forceinline__ void ldm_x4(uint32_t* r, uint32_t a) {
    asm volatile("ldmatrix.sync.aligned.m8n8.x4.shared.b16 {%0,%1,%2,%3}, [%4];"
        : "=r"(r[0]), "=r"(r[1]), "=r"(r[2]), "=r"(r[3]) : "r"(a));
}
__device__ __forceinline__ void ldm_x4_t(uint32_t* r, uint32_t a) {
    asm volatile("ldmatrix.sync.aligned.m8n8.x4.trans.shared.b16 {%0,%1,%2,%3}, [%4];"
        : "=r"(r[0]), "=r"(r[1]), "=r"(r[2]), "=r"(r[3]) : "r"(a));
}
__device__ __forceinline__ void mma16816h(float* c, const uint32_t* a, const uint32_t* b) {
    asm volatile("mma.sync.aligned.m16n8k16.row.col.f32.f16.f16.f32 "
        "{%0,%1,%2,%3}, {%4,%5,%6,%7}, {%8,%9}, {%0,%1,%2,%3};"
        : "+f"(c[0]), "+f"(c[1]), "+f"(c[2]), "+f"(c[3])
        : "r"(a[0]), "r"(a[1]), "r"(a[2]), "r"(a[3]), "r"(b[0]), "r"(b[1]));
}

// ---------------- mask dtype detection + packing ----------------------------------
__global__ void detect_mask_kernel(const void* m) {
    __shared__ int cu, ci, cf;
    if (threadIdx.x == 0) { cu = 0; ci = 0; cf = 0; }
    __syncthreads();
    const unsigned char* u8 = (const unsigned char*)m;
    const int*   i32 = (const int*)m;
    const float* f32 = (const float*)m;
    int lu = 0;
    for (int i = threadIdx.x; i < SEQ; i += 256)
        if (u8[(size_t)i*(SEQ+1)]) lu++;
    atomicAdd(&cu, lu);
    if (threadIdx.x < 250) {
        if (i32[(size_t)threadIdx.x*(SEQ+1)] != 0)    atomicAdd(&ci, 1);
        if (f32[(size_t)threadIdx.x*(SEQ+1)] == 1.0f) atomicAdd(&cf, 1);
    }
    __syncthreads();
    if (threadIdx.x == 0)
        g_mask_mode = (cu == SEQ) ? 0 : (cf == 250) ? 2 : (ci == 250) ? 1 : 0;
}

__global__ void pack_mask_kernel(const void* m) {
    int w = blockIdx.x * blockDim.x + threadIdx.x;
    if (w >= SEQ*SEQ/32) return;
    int mode = g_mask_mode;
    size_t base = (size_t)w * 32;
    unsigned out = 0;
    if (mode == 0) {
        const unsigned char* p = (const unsigned char*)m;
        #pragma unroll
        for (int j = 0; j < 32; j++) if (p[base+j]) out |= 1u << j;
    } else if (mode == 1) {
        const int* p = (const int*)m;
        #pragma unroll
        for (int j = 0; j < 32; j++) if (p[base+j] != 0) out |= 1u << j;
    } else {
        const float* p = (const float*)m;
        #pragma unroll
        for (int j = 0; j < 32; j++) if (p[base+j] != 0.0f) out |= 1u << j;
    }
    g_maskbits[w] = out;
}

// ---------------- fp32 -> fp16, row-major -----------------------------------------
__global__ __launch_bounds__(256) void convert_h_kernel(
    const float* __restrict__ src, __half* __restrict__ hi, int n4)
{
    int t = blockIdx.x * 256 + threadIdx.x;
    if (t >= n4) return;
    float4 v = *(const float4*)(src + (size_t)t * 4);
    *(uint2*)(hi + (size_t)t * 4) = make_uint2(
        pk2h(__float2half(v.x), __float2half(v.y)),
        pk2h(__float2half(v.z), __float2half(v.w)));
}

// fp32 -> fp16, 4 weights (blockIdx.y selects)
__global__ __launch_bounds__(256) void convert_w4_kernel(
    const float* w0, const float* w1, const float* w2, const float* w3, int n4)
{
    int t = blockIdx.x * 256 + threadIdx.x;
    if (t >= n4) return;
    int z = blockIdx.y;
    const float* src = (z == 0) ? w0 : (z == 1) ? w1 : (z == 2) ? w2 : w3;
    __half* hi = g_w_hi[z];
    float4 v = *(const float4*)(src + (size_t)t * 4);
    *(uint2*)(hi + (size_t)t * 4) = make_uint2(
        pk2h(__float2half(v.x), __float2half(v.y)),
        pk2h(__float2half(v.z), __float2half(v.w)));
}

// ---------------- pure-fp16 HMMA GEMM: C = Ahi·Whi --------------------------------
// 128x128 CTA tile, 256 threads (8 warps 4x2), k16 steps, 2-stage cp.async.
// Stage = Ahi + Bhi (12KB). z==2 writes fp16 (V path).
#define GS_ROW   24
#define GS_ARR   (128*GS_ROW*2)            // 6144 B per array
#define GS_BUF   (2*GS_ARR)                // 12288 B per stage
#define GS_TOTAL (2*GS_BUF)                // 24576 B

__global__ __launch_bounds__(256, 2) void gemm_hmma_kernel(
    const __half* __restrict__ ahi,
    const __half* w0h, float* c0,
    const __half* w1h, float* c1,
    const __half* w2h, __half* c2h)
{
    extern __shared__ char sm[];
    uint32_t sb = smem_u32(sm);
    int tid = threadIdx.x, wid = tid >> 5, lane = tid & 31;
    int bn0 = blockIdx.x * 128, bm0 = blockIdx.y * 128, z = blockIdx.z;
    const __half* wh = (z == 0) ? w0h : (z == 1) ? w1h : w2h;

    int wm = wid >> 1, wn = wid & 1;

    int lrow = tid >> 1, lhalf = tid & 1;
    const __half* gA_hi = ahi + (size_t)(bm0 + lrow) * DIM + lhalf * 8;
    const __half* gB_hi = wh  + (size_t)(bn0 + lrow) * DIM + lhalf * 8;
    uint32_t sOff = (uint32_t)(lrow * GS_ROW + lhalf * 8) * 2;

    float acc[2][8][4];
    #pragma unroll
    for (int i = 0; i < 2; i++)
        #pragma unroll
        for (int j = 0; j < 8; j++)
            #pragma unroll
            for (int r = 0; r < 4; r++) acc[i][j][r] = 0.0f;

    uint32_t aRowByte = (uint32_t)((wm*32 + (lane & 15)) * GS_ROW + (lane >> 4) * 8) * 2;
    uint32_t bRowByte = (uint32_t)((wn*64 + ((lane >> 4) & 1)*8 + (lane & 7)) * GS_ROW
                                   + ((lane >> 3) & 1) * 8) * 2;

    {
        uint32_t s0 = sb + sOff;
        cp16(s0,          gA_hi);
        cp16(s0 + GS_ARR, gB_hi);
        asm volatile("cp.async.commit_group;");
    }

    for (int ks = 0; ks < 64; ks++) {
        int cur = ks & 1;
        if (ks < 63) {
            uint32_t s0 = sb + (cur ^ 1) * GS_BUF + sOff;
            int k0 = (ks + 1) * 16;
            cp16(s0,          gA_hi + k0);
            cp16(s0 + GS_ARR, gB_hi + k0);
            asm volatile("cp.async.commit_group;");
            asm volatile("cp.async.wait_group 1;");
        } else {
            asm volatile("cp.async.wait_group 0;");
        }
        __syncthreads();

        uint32_t bufb = sb + cur * GS_BUF;

        uint32_t ah[2][4];
        #pragma unroll
        for (int mf = 0; mf < 2; mf++)
            ldm_x4(ah[mf], bufb + aRowByte + (uint32_t)(mf * 16 * GS_ROW) * 2);
        #pragma unroll
        for (int pr = 0; pr < 4; pr++) {
            uint32_t bhv[4];
            ldm_x4(bhv, bufb + GS_ARR + bRowByte + (uint32_t)(pr * 16 * GS_ROW) * 2);
            #pragma unroll
            for (int mf = 0; mf < 2; mf++) {
                mma16816h(acc[mf][2*pr],   ah[mf], bhv);
                mma16816h(acc[mf][2*pr+1], ah[mf], bhv+2);
            }
        }
        __syncthreads();
    }

    int gid4 = lane >> 2, l4 = lane & 3;
    if (z == 2) {
        // V projection: write fp16 directly for the attention kernel
        #pragma unroll
        for (int mf = 0; mf < 2; mf++) {
            int row = bm0 + wm*32 + mf*16 + gid4;
            #pragma unroll
            for (int nf = 0; nf < 8; nf++) {
                int col = bn0 + wn*64 + nf*8 + l4*2;
                *(uint32_t*)(c2h + (size_t)row * DIM + col) =
                    pk2h(__float2half(acc[mf][nf][0]), __float2half(acc[mf][nf][1]));
                *(uint32_t*)(c2h + (size_t)(row + 8) * DIM + col) =
                    pk2h(__float2half(acc[mf][nf][2]), __float2half(acc[mf][nf][3]));
            }
        }
    } else {
        float* C = (z == 0) ? c0 : c1;
        #pragma unroll
        for (int mf = 0; mf < 2; mf++) {
            int row = bm0 + wm*32 + mf*16 + gid4;
            #pragma unroll
            for (int nf = 0; nf < 8; nf++) {
                int col = bn0 + wn*64 + nf*8 + l4*2;
                *(float2*)(C + (size_t)row * DIM + col) =
                    make_float2(acc[mf][nf][0], acc[mf][nf][1]);
                *(float2*)(C + (size_t)(row + 8) * DIM + col) =
                    make_float2(acc[mf][nf][2], acc[mf][nf][3]);
            }
        }
    }
}

// ---------------- QKNorm + RoPE -> fp16 (Q and K) ---------------------------------
__global__ __launch_bounds__(256) void norm_rope_kernel(
    const float* __restrict__ qg, const float* __restrict__ kg,
    const float* __restrict__ cosb, const float* __restrict__ sinb,
    const int* __restrict__ ridx)
{
    int task = blockIdx.x * 8 + (threadIdx.x >> 5);
    int t = threadIdx.x & 31;
    int which = task >> 17;
    int rem = task & 0x1FFFF;
    int head = rem & (NHEAD - 1);
    int tok  = rem >> 4;
    const float* base = (which ? g_k : g_q) + (size_t)tok * DIM + head * HDIM;
    const float* gamma = which ? kg : qg;
    float x0 = base[t], x1 = base[t + 32];
    float ss = x0*x0 + x1*x1;
    #pragma unroll
    for (int off = 16; off >= 1; off >>= 1)
        ss += __shfl_xor_sync(0xffffffffu, ss, off);
    float r = rsqrtf(ss * (1.0f/64.0f) + EPSN);
    float n0 = x0 * r * gamma[t];
    float n1 = x1 * r * gamma[t + 32];
    int idx = ridx[tok & (SEQ - 1)];
    if (idx >= 0) {
        const float* cp = cosb + (size_t)idx * HDIM;
        const float* sp = sinb + (size_t)idx * HDIM;
        float o0 = n0 * cp[t]      - n1 * sp[t];
        float o1 = n1 * cp[t + 32] + n0 * sp[t + 32];
        n0 = o0; n1 = o1;
    }
    __half* dh = (which ? g_kbh : g_qbh) + (size_t)tok * DIM + head * HDIM;
    dh[t]      = __float2half(n0);
    dh[t + 32] = __float2half(n1);
}

// ---------------- tensor-core flash attention, pure fp16 (R14, passed) ------------
#define A_STR   144
#define A_QH    0
#define A_ST0   (128*A_STR)                 // 18432
#define A_KH    0
#define A_VH    18432
#define A_STAGE 36864
#define A_SMEM  (A_ST0 + 2*A_STAGE)         // 92160

__global__ __launch_bounds__(256, 1) void attn_tc_kernel() {
    extern __shared__ char smc[];
    uint32_t sb = smem_u32(smc);
    int tid = threadIdx.x, wid = tid >> 5, lane = tid & 31;
    int qt = blockIdx.x, h = blockIdx.y, b = blockIdx.z;
    int gid4 = lane >> 2, l4 = lane & 3;

    size_t qtok0 = (size_t)(b*SEQ + qt*128);

    #pragma unroll
    for (int i = 0; i < 4; i++) {
        int id = tid + i*256;
        int r = id >> 3, ch = id & 7;
        size_t gq = (qtok0 + r) * DIM + h*HDIM + ch*8;
        cp16(sb + A_QH + r*A_STR + ch*16, g_qbh + gq);
        size_t gk = ((size_t)(b*SEQ + r)) * DIM + h*HDIM + ch*8;
        uint32_t st = sb + A_ST0;
        cp16(st + A_KH + r*A_STR + ch*16, g_kbh + gk);
        cp16(st + A_VH + r*A_STR + ch*16, g_vbh + gk);
    }
    asm volatile("cp.async.commit_group;");
    asm volatile("cp.async.wait_group 0;");
    __syncthreads();

    uint32_t qfh[4][4];
    {
        uint32_t arow = (uint32_t)(wid*16 + (lane & 15));
        uint32_t acol = (uint32_t)((lane >> 4) * 16);
        #pragma unroll
        for (int ks = 0; ks < 4; ks++)
            ldm_x4(qfh[ks], sb + A_QH + arow*A_STR + ks*32 + acol);
    }

    float o[8][4];
    #pragma unroll
    for (int i = 0; i < 8; i++)
        #pragma unroll
        for (int j = 0; j < 4; j++) o[i][j] = 0.0f;
    float m0 = NEGINF, m1 = NEGINF, l0 = 0.0f, l1 = 0.0f;

    int qr0 = qt*128 + wid*16 + gid4;
    uint32_t brow = (uint32_t)(((lane >> 4) & 1)*8 + (lane & 7));
    uint32_t bcol = (uint32_t)(((lane >> 3) & 1) * 16);
    uint32_t vrow = (uint32_t)(((lane >> 3) & 1)*8 + (lane & 7));
    uint32_t vcol = (uint32_t)((lane >> 4) * 16);

    for (int kt = 0; kt < 8; kt++) {
        uint32_t st = sb + A_ST0 + (uint32_t)(kt & 1)*A_STAGE;
        if (kt < 7) {
            uint32_t sn = sb + A_ST0 + (uint32_t)((kt+1) & 1)*A_STAGE;
            #pragma unroll
            for (int i = 0; i < 4; i++) {
                int id = tid + i*256;
                int r = id >> 3, ch = id & 7;
                size_t g = ((size_t)(b*SEQ + (kt+1)*128 + r)) * DIM + h*HDIM + ch*8;
                cp16(sn + A_KH + r*A_STR + ch*16, g_kbh + g);
                cp16(sn + A_VH + r*A_STR + ch*16, g_vbh + g);
            }
            asm volatile("cp.async.commit_group;");
            asm volatile("cp.async.wait_group 1;");
        } else {
            asm volatile("cp.async.wait_group 0;");
        }
        __syncthreads();

        // ---- S = Qhi Khi^T ----
        float c[16][4];
        #pragma unroll
        for (int i = 0; i < 16; i++)
            #pragma unroll
            for (int j = 0; j < 4; j++) c[i][j] = 0.0f;
        #pragma unroll
        for (int ks = 0; ks < 4; ks++) {
            #pragma unroll
            for (int np = 0; np < 8; np++) {
                uint32_t kb[4];
                uint32_t off = (uint32_t)(np*16 + brow)*A_STR + ks*32 + bcol;
                ldm_x4(kb, st + A_KH + off);
                mma16816h(c[2*np],   qfh[ks], kb);
                mma16816h(c[2*np+1], qfh[ks], kb+2);
            }
        }

        unsigned w0[4], w1[4];
        #pragma unroll
        for (int w = 0; w < 4; w++) {
            w0[w] = g_maskbits[qr0*32 + kt*4 + w];
            w1[w] = g_maskbits[(qr0+8)*32 + kt*4 + w];
        }
        float tm0 = NEGINF, tm1 = NEGINF;
        #pragma unroll
        for (int nf = 0; nf < 16; nf++) {
            int word = nf >> 2;
            int bit = (nf & 3)*8 + l4*2;
            #pragma unroll
            for (int e = 0; e < 4; e++) {
                float y  = c[nf][e] * (SCALE / CAP);
                float y2 = y * y;
                float a  = CAP * (y * (1.0f + y2 * (-0.3333333433f + y2 * 0.1333333403f)));
                unsigned wv = (e < 2) ? w0[word] : w1[word];
                c[nf][e] = ((wv >> (bit + (e & 1))) & 1u) ? a : NEGINF;
            }
            tm0 = fmaxf(tm0, fmaxf(c[nf][0], c[nf][1]));
            tm1 = fmaxf(tm1, fmaxf(c[nf][2], c[nf][3]));
        }
        tm0 = fmaxf(tm0, __shfl_xor_sync(0xffffffffu, tm0, 1));
        tm0 = fmaxf(tm0, __shfl_xor_sync(0xffffffffu, tm0, 2));
        tm1 = fmaxf(tm1, __shfl_xor_sync(0xffffffffu, tm1, 1));
        tm1 = fmaxf(tm1, __shfl_xor_sync(0xffffffffu, tm1, 2));
        float mn0 = fmaxf(m0, tm0), mn1 = fmaxf(m1, tm1);
        float al0 = __expf(m0 - mn0), al1 = __expf(m1 - mn1);
        m0 = mn0; m1 = mn1;
        float rs0 = 0.0f, rs1 = 0.0f;
        #pragma unroll
        for (int nf = 0; nf < 16; nf++) {
            c[nf][0] = __expf(c[nf][0] - mn0);
            c[nf][1] = __expf(c[nf][1] - mn0);
            c[nf][2] = __expf(c[nf][2] - mn1);
            c[nf][3] = __expf(c[nf][3] - mn1);
            rs0 += c[nf][0] + c[nf][1];
            rs1 += c[nf][2] + c[nf][3];
        }
        rs0 += __shfl_xor_sync(0xffffffffu, rs0, 1);
        rs0 += __shfl_xor_sync(0xffffffffu, rs0, 2);
        rs1 += __shfl_xor_sync(0xffffffffu, rs1, 1);
        rs1 += __shfl_xor_sync(0xffffffffu, rs1, 2);
        l0 = l0 * al0 + rs0;
        l1 = l1 * al1 + rs1;
        #pragma unroll
        for (int nf = 0; nf < 8; nf++) {
            o[nf][0] *= al0; o[nf][1] *= al0; o[nf][2] *= al1; o[nf][3] *= al1;
        }

        // ---- O += Phi Vhi ----
        #pragma unroll
        for (int ks = 0; ks < 8; ks++) {
            uint32_t pah[4];
            pah[0] = pk2h(__float2half(c[2*ks][0]),   __float2half(c[2*ks][1]));
            pah[1] = pk2h(__float2half(c[2*ks][2]),   __float2half(c[2*ks][3]));
            pah[2] = pk2h(__float2half(c[2*ks+1][0]), __float2half(c[2*ks+1][1]));
            pah[3] = pk2h(__float2half(c[2*ks+1][2]), __float2half(c[2*ks+1][3]));
            #pragma unroll
            for (int npv = 0; npv < 4; npv++) {
                uint32_t vb[4];
                uint32_t off = (uint32_t)(ks*16 + vrow)*A_STR + npv*32 + vcol;
                ldm_x4_t(vb, st + A_VH + off);
                mma16816h(o[2*npv],   pah, vb);
                mma16816h(o[2*npv+1], pah, vb+2);
            }
        }
        __syncthreads();
    }

    // epilogue: normalize, write fp16 for the O projection
    float inv0 = 1.0f / l0, inv1 = 1.0f / l1;
    size_t r0g = (qtok0 + wid*16 + gid4) * DIM + h*HDIM;
    size_t r1g = r0g + (size_t)8 * DIM;
    #pragma unroll
    for (int nf = 0; nf < 8; nf++) {
        int col = nf*8 + l4*2;
        *(uint32_t*)(g_att_hi + r0g + col) =
            pk2h(__float2half(o[nf][0]*inv0), __float2half(o[nf][1]*inv0));
        *(uint32_t*)(g_att_hi + r1g + col) =
            pk2h(__float2half(o[nf][2]*inv1), __float2half(o[nf][3]*inv1));
    }
}

// ---------------- launch ----------------------------------------------------------
extern "C" void kernel_launch(void* const* d_in, const int* in_sizes, int n_in,
                              void* d_out, int out_size)
{
    const float* x    = (const float*)d_in[0];
    const float* Wq   = (const float*)d_in[1];
    const float* Wk   = (const float*)d_in[2];
    const float* Wv   = (const float*)d_in[3];
    const float* Wo   = (const float*)d_in[4];
    const float* qg   = (const float*)d_in[5];
    const float* kg   = (const float*)d_in[6];
    const float* cosb = (const float*)d_in[7];
    const float* sinb = (const float*)d_in[8];
    const int*   ridx = (const int*)d_in[9];
    const void*  mask = d_in[10];
    float* out = (float*)d_out;

    float *gq, *gk;
    __half *xhi, *athi, *whB, *vbh;
    cudaGetSymbolAddress((void**)&gq,   g_q);
    cudaGetSymbolAddress((void**)&gk,   g_k);
    cudaGetSymbolAddress((void**)&xhi,  g_x_hi);
    cudaGetSymbolAddress((void**)&athi, g_att_hi);
    cudaGetSymbolAddress((void**)&whB,  g_w_hi);
    cudaGetSymbolAddress((void**)&vbh,  g_vbh);
    __half *wqh = whB;
    __half *wkh = whB + 1*DIM*DIM;
    __half *wvh = whB + 2*DIM*DIM;
    __half *woh = whB + 3*DIM*DIM;

    cudaFuncSetAttribute(gemm_hmma_kernel,
        cudaFuncAttributeMaxDynamicSharedMemorySize, GS_TOTAL);
    cudaFuncSetAttribute(attn_tc_kernel,
        cudaFuncAttributeMaxDynamicSharedMemorySize, A_SMEM);

    // QKV GEMM kept at launch position 4 for ncu capture.
    detect_mask_kernel<<<1, 256>>>(mask);                                            // 1
    convert_h_kernel<<<(MTOT*DIM/4 + 255)/256, 256>>>(x, xhi, MTOT*DIM/4);           // 2
    convert_w4_kernel<<<dim3((DIM*DIM/4 + 255)/256, 4), 256>>>(                      // 3
        Wq, Wk, Wv, Wo, DIM*DIM/4);

    gemm_hmma_kernel<<<dim3(8, 64, 3), 256, GS_TOTAL>>>(                             // 4 (QKV; V->fp16)
        xhi, wqh, gq, wkh, gk, wvh, vbh);

    pack_mask_kernel<<<(SEQ*SEQ/32 + 255)/256, 256>>>(mask);                         // 5
    norm_rope_kernel<<<(2*MTOT*NHEAD)/8, 256>>>(qg, kg, cosb, sinb, ridx);           // 6

    attn_tc_kernel<<<dim3(SEQ/128, NHEAD, BATCH), 256, A_SMEM>>>();                  // 7

    gemm_hmma_kernel<<<dim3(8, 64, 1), 256, GS_TOTAL>>>(                             // 8 (O)
        athi, woh, out, woh, out, woh, (half*)out /*unused*/);
}